// round 14
// baseline (speedup 1.0000x reference)
#include <cuda_runtime.h>
#include <cuda_bf16.h>
#include <cuda_fp16.h>
#include <cstdint>
#include <cstddef>

#define Bb 2
#define Ss 2048
#define Hh 1024
#define NHh 16
#define HDd 64
#define NTt 5
#define TOKS (Bb*Ss)          /* 4096 */
#define SCALE 0.125f          /* 1/sqrt(64) */

// ---------------- scratch (static device globals; no allocation) ----------------
__device__ float g_qt[(size_t)TOKS*HDd];
__device__ __half g_xf[(size_t)TOKS*Hh];
__device__ __half g_wf[(size_t)3*Hh*Hh];
__device__ __nv_bfloat16 g_xhi[(size_t)TOKS*Hh];   /* attn-output hi (reused) */
__device__ __nv_bfloat16 g_xlo[(size_t)TOKS*Hh];   /* attn-output lo (reused) */
__device__ __nv_bfloat16 g_whi[(size_t)Hh*Hh];     /* Wo hi */
__device__ __nv_bfloat16 g_wlo[(size_t)Hh*Hh];     /* Wo lo */
__device__ __half g_qf[(size_t)TOKS*Hh];
__device__ __half g_kf[(size_t)TOKS*Hh];
__device__ __half g_vf[(size_t)TOKS*Hh];
__device__ __nv_bfloat16 g_kthi[(size_t)TOKS*HDd];
__device__ __nv_bfloat16 g_ktlo[(size_t)TOKS*HDd];
__device__ __nv_bfloat16 g_qwhi[(size_t)Bb*NHh*Ss*HDd];
__device__ __nv_bfloat16 g_qwlo[(size_t)Bb*NHh*Ss*HDd];

// ================= low-level helpers (all plain sm_80+ features) =================
__device__ __forceinline__ uint32_t smem_u32(const void* p) {
    uint32_t a;
    asm("{ .reg .u64 t; cvta.to.shared.u64 t, %1; cvt.u32.u64 %0, t; }" : "=r"(a) : "l"(p));
    return a;
}
#define CP_ASYNC16(saddr, gaddr) \
    asm volatile("cp.async.cg.shared.global [%0], [%1], 16;" :: "r"(saddr), "l"(gaddr))
#define CP_COMMIT() asm volatile("cp.async.commit_group;" ::: "memory")
#define CP_WAIT1()  asm volatile("cp.async.wait_group 1;" ::: "memory")
#define CP_WAIT0()  asm volatile("cp.async.wait_group 0;" ::: "memory")
#define LDSM_X4(r0, r1, r2, r3, addr) \
    asm volatile("ldmatrix.sync.aligned.m8n8.x4.shared.b16 {%0,%1,%2,%3}, [%4];" \
        : "=r"(r0), "=r"(r1), "=r"(r2), "=r"(r3) : "r"(addr))
#define LDSM_X4_T(r0, r1, r2, r3, addr) \
    asm volatile("ldmatrix.sync.aligned.m8n8.x4.trans.shared.b16 {%0,%1,%2,%3}, [%4];" \
        : "=r"(r0), "=r"(r1), "=r"(r2), "=r"(r3) : "r"(addr))
#define MMA16816(c, a, b0, b1) \
    asm volatile("mma.sync.aligned.m16n8k16.row.col.f32.bf16.bf16.f32 " \
        "{%0,%1,%2,%3}, {%4,%5,%6,%7}, {%8,%9}, {%0,%1,%2,%3};" \
        : "+f"((c)[0]), "+f"((c)[1]), "+f"((c)[2]), "+f"((c)[3]) \
        : "r"((a)[0]), "r"((a)[1]), "r"((a)[2]), "r"((a)[3]), "r"(b0), "r"(b1))
#define MMAF16(c, a, b0, b1) \
    asm volatile("mma.sync.aligned.m16n8k16.row.col.f32.f16.f16.f32 " \
        "{%0,%1,%2,%3}, {%4,%5,%6,%7}, {%8,%9}, {%0,%1,%2,%3};" \
        : "+f"((c)[0]), "+f"((c)[1]), "+f"((c)[2]), "+f"((c)[3]) \
        : "r"((a)[0]), "r"((a)[1]), "r"((a)[2]), "r"((a)[3]), "r"(b0), "r"(b1))

__device__ __forceinline__ void split2(float x, float y, uint32_t& hi, uint32_t& lo) {
    __nv_bfloat16 hx = __float2bfloat16(x), hy = __float2bfloat16(y);
    __nv_bfloat16 lx = __float2bfloat16(x - __bfloat162float(hx));
    __nv_bfloat16 ly = __float2bfloat16(y - __bfloat162float(hy));
    __nv_bfloat162 h2(hx, hy), l2(lx, ly);
    hi = *(uint32_t*)&h2; lo = *(uint32_t*)&l2;
}
__device__ __forceinline__ uint32_t packh2(float x, float y) {
    __half2 h = __floats2half2_rn(x, y);
    return *(uint32_t*)&h;
}

// ================= conversions =================
// fp32 -> fp16 single (x and Wq/Wk/Wv), 4 float4 per thread
__global__ __launch_bounds__(256)
void cvt_f16(const float4* __restrict__ in, __half* __restrict__ out, int n4)
{
    int base = blockIdx.x * 1024 + threadIdx.x;
    float4 f[4];
    int idx[4];
#pragma unroll
    for (int u = 0; u < 4; u++) {
        idx[u] = base + u * 256;
        if (idx[u] < n4) f[u] = in[idx[u]];
    }
#pragma unroll
    for (int u = 0; u < 4; u++) {
        if (idx[u] >= n4) continue;
        uint2 o;
        o.x = packh2(f[u].x, f[u].y);
        o.y = packh2(f[u].z, f[u].w);
        *(uint2*)(out + (size_t)idx[u] * 4) = o;
    }
}

// Wq/Wk/Wv -> fp16 in one launch (grid.y selects)
__global__ __launch_bounds__(256)
void cvt_f16_w3(const float4* __restrict__ W0, const float4* __restrict__ W1,
                const float4* __restrict__ W2, __half* __restrict__ out)
{
    const int n4 = Hh * Hh / 4;
    int z = blockIdx.y;
    const float4* in = (z == 0) ? W0 : (z == 1) ? W1 : W2;
    int base = blockIdx.x * 1024 + threadIdx.x;
    float4 f[4];
    int idx[4];
#pragma unroll
    for (int u = 0; u < 4; u++) {
        idx[u] = base + u * 256;
        if (idx[u] < n4) f[u] = in[idx[u]];
    }
    size_t zb = (size_t)z * Hh * Hh;
#pragma unroll
    for (int u = 0; u < 4; u++) {
        if (idx[u] >= n4) continue;
        uint2 o;
        o.x = packh2(f[u].x, f[u].y);
        o.y = packh2(f[u].z, f[u].w);
        *(uint2*)(out + zb + (size_t)idx[u] * 4) = o;
    }
}

// fp32 -> bf16 hi/lo split (Wo only), 4 float4 per thread
__global__ __launch_bounds__(256)
void cvt_split(const float4* __restrict__ in, __nv_bfloat162* __restrict__ hi,
               __nv_bfloat162* __restrict__ lo, int n4)
{
    int base = blockIdx.x * 1024 + threadIdx.x;
    float4 f[4];
    int idx[4];
#pragma unroll
    for (int u = 0; u < 4; u++) {
        idx[u] = base + u * 256;
        if (idx[u] < n4) f[u] = in[idx[u]];
    }
#pragma unroll
    for (int u = 0; u < 4; u++) {
        if (idx[u] >= n4) continue;
        uint32_t h0, l0, h1, l1;
        split2(f[u].x, f[u].y, h0, l0);
        split2(f[u].z, f[u].w, h1, l1);
        ((uint32_t*)hi)[2*idx[u]]   = h0; ((uint32_t*)hi)[2*idx[u]+1] = h1;
        ((uint32_t*)lo)[2*idx[u]]   = l0; ((uint32_t*)lo)[2*idx[u]+1] = l1;
    }
}

// ================= fp16 single-term GEMM: q/k/v = x @ W^T + b (fp16 out) =================
#define GN 1024
#define GF_BUF 32768
#define GF_SMEM (2*GF_BUF + 512)

__global__ __launch_bounds__(256)
void gemm_qkv_f16(const __half* __restrict__ xf, const __half* __restrict__ wf,
                  const float* __restrict__ bq, const float* __restrict__ bk,
                  const float* __restrict__ bv,
                  __half* __restrict__ qf, __half* __restrict__ kf, __half* __restrict__ vf)
{
    extern __shared__ char sm_[];
    uint32_t sb = smem_u32(sm_);
    float* bias_s = (float*)(sm_ + 2 * GF_BUF);
    int z = blockIdx.z;
    const __half* Wf = wf + (size_t)z * Hh * Hh;
    const float* bias = (z == 0) ? bq : (z == 1) ? bk : bv;
    __half* Ch = (z == 0) ? qf : (z == 1) ? kf : vf;
    float oscale = (z == 0) ? SCALE : 1.f;

    int tid = threadIdx.x, wid = tid >> 5, lid = tid & 31;
    int bm = blockIdx.y * 128, bn = blockIdx.x * 128;
    if (tid < 128) bias_s[tid] = bias[bn + tid];

    int warp_row = (wid & 1) * 64;
    int warp_col = (wid >> 1) * 32;
    int sub = lid & 7;
    int gA1 = (lid >> 3) & 1, ca = (lid >> 4) & 1;
    int gB2 = (lid >> 4) & 1, cb = (lid >> 3) & 1;

    uint32_t aBase[4], bBase[2];
#pragma unroll
    for (int i = 0; i < 4; i++)
        aBase[i] = (uint32_t)((warp_row + i * 16 + gA1 * 8 + sub) * 128);
#pragma unroll
    for (int p = 0; p < 2; p++)
        bBase[p] = (uint32_t)((warp_col + p * 16 + gB2 * 8 + sub) * 128);

    float acc[4][4][4];
#pragma unroll
    for (int i = 0; i < 4; i++)
#pragma unroll
        for (int jn = 0; jn < 4; jn++)
#pragma unroll
            for (int r = 0; r < 4; r++) acc[i][jn][r] = 0.f;

    // prologue load chunk 0
#pragma unroll
    for (int i = tid; i < 1024; i += 256) {
        int r = i >> 3, c = i & 7;
        uint32_t sw = (uint32_t)(r * 128) + (uint32_t)((c ^ (r & 7)) << 4);
        CP_ASYNC16(sb + sw,           (const char*)xf + (((size_t)(bm + r)) << 11) + (c << 4));
        CP_ASYNC16(sb + 16384 + sw,   (const char*)Wf + (((size_t)(bn + r)) << 11) + (c << 4));
    }
    CP_COMMIT();

    for (int c = 0; c < 16; c++) {
        if (c + 1 < 16) {
            uint32_t nbuf = sb + ((c + 1) & 1) * GF_BUF;
            int kcb = (c + 1) * 128;
#pragma unroll
            for (int i = tid; i < 1024; i += 256) {
                int r = i >> 3, cc = i & 7;
                uint32_t sw = (uint32_t)(r * 128) + (uint32_t)((cc ^ (r & 7)) << 4);
                CP_ASYNC16(nbuf + sw,         (const char*)xf + (((size_t)(bm + r)) << 11) + kcb + (cc << 4));
                CP_ASYNC16(nbuf + 16384 + sw, (const char*)Wf + (((size_t)(bn + r)) << 11) + kcb + (cc << 4));
            }
            CP_COMMIT();
            CP_WAIT1();
        } else {
            CP_WAIT0();
        }
        __syncthreads();

        uint32_t bufoff = sb + (c & 1) * GF_BUF;
#pragma unroll
        for (int j = 0; j < 4; j++) {
            uint32_t ah[4][4], bh[2][4];
#pragma unroll
            for (int i = 0; i < 4; i++) {
                uint32_t ad = bufoff + aBase[i] + (uint32_t)(((2 * j + ca) ^ sub) << 4);
                LDSM_X4(ah[i][0], ah[i][1], ah[i][2], ah[i][3], ad);
            }
#pragma unroll
            for (int p = 0; p < 2; p++) {
                uint32_t bd = bufoff + 16384 + bBase[p] + (uint32_t)(((2 * j + cb) ^ sub) << 4);
                LDSM_X4(bh[p][0], bh[p][1], bh[p][2], bh[p][3], bd);
            }
#pragma unroll
            for (int i = 0; i < 4; i++) {
#pragma unroll
                for (int jn = 0; jn < 4; jn++) {
                    int p = jn >> 1, q = (jn & 1) * 2;
                    MMAF16(acc[i][jn], ah[i], bh[p][q], bh[p][q + 1]);
                }
            }
        }
        __syncthreads();
    }

    int lr = lid >> 2, lc = (lid & 3) * 2;
#pragma unroll
    for (int i = 0; i < 4; i++) {
#pragma unroll
        for (int jn = 0; jn < 4; jn++) {
            int row = bm + warp_row + i * 16 + lr;
            int colL = warp_col + jn * 8 + lc;
            int col = bn + colL;
            float b0 = bias_s[colL], b1 = bias_s[colL + 1];
            float v00 = (acc[i][jn][0] + b0) * oscale, v01 = (acc[i][jn][1] + b1) * oscale;
            float v10 = (acc[i][jn][2] + b0) * oscale, v11 = (acc[i][jn][3] + b1) * oscale;
            *(uint32_t*)(Ch + (size_t)row * GN + col)       = packh2(v00, v01);
            *(uint32_t*)(Ch + (size_t)(row + 8) * GN + col) = packh2(v10, v11);
        }
    }
}

// ================= bf16-split GEMM (O projection only): y = attn @ Wo^T + bo =================
#define BUF_BYTES 65536
#define OFF_AL 16384
#define OFF_WH 32768
#define OFF_WL 49152
#define GEMM_SMEM (2*BUF_BYTES + 512)

__global__ __launch_bounds__(256)
void gemm_o(const __nv_bfloat16* __restrict__ Ahi, const __nv_bfloat16* __restrict__ Alo,
            const __nv_bfloat16* __restrict__ Whi, const __nv_bfloat16* __restrict__ Wlo,
            const float* __restrict__ bias, float* __restrict__ Cf)
{
    extern __shared__ char sm_[];
    uint32_t sb = smem_u32(sm_);
    float* bias_s = (float*)(sm_ + 2 * BUF_BYTES);
    int tid = threadIdx.x, wid = tid >> 5, lid = tid & 31;
    int bm = blockIdx.y * 128, bn = blockIdx.x * 128;

    if (tid < 128) bias_s[tid] = bias[bn + tid];

    int warp_row = (wid & 1) * 64;
    int warp_col = (wid >> 1) * 32;
    int sub = lid & 7;
    int gA1 = (lid >> 3) & 1, ca = (lid >> 4) & 1;
    int gB2 = (lid >> 4) & 1, cb = (lid >> 3) & 1;

    uint32_t aBase[4], bBase[2];
#pragma unroll
    for (int i = 0; i < 4; i++)
        aBase[i] = (uint32_t)((warp_row + i * 16 + gA1 * 8 + sub) * 128);
#pragma unroll
    for (int p = 0; p < 2; p++)
        bBase[p] = (uint32_t)((warp_col + p * 16 + gB2 * 8 + sub) * 128);

    float acc[4][4][4];
#pragma unroll
    for (int i = 0; i < 4; i++)
#pragma unroll
        for (int jn = 0; jn < 4; jn++)
#pragma unroll
            for (int r = 0; r < 4; r++) acc[i][jn][r] = 0.f;

#pragma unroll
    for (int i = tid; i < 1024; i += 256) {
        int r = i >> 3, c = i & 7;
        uint32_t sw = (uint32_t)(r * 128) + (uint32_t)((c ^ (r & 7)) << 4);
        size_t goA = ((size_t)(bm + r) << 11) + (c << 4);
        size_t goW = ((size_t)(bn + r) << 11) + (c << 4);
        CP_ASYNC16(sb + sw,          (const char*)Ahi + goA);
        CP_ASYNC16(sb + OFF_AL + sw, (const char*)Alo + goA);
        CP_ASYNC16(sb + OFF_WH + sw, (const char*)Whi + goW);
        CP_ASYNC16(sb + OFF_WL + sw, (const char*)Wlo + goW);
    }
    CP_COMMIT();

    for (int c = 0; c < 16; c++) {
        if (c + 1 < 16) {
            uint32_t nbuf = sb + ((c + 1) & 1) * BUF_BYTES;
            int kcb = (c + 1) * 128;
#pragma unroll
            for (int i = tid; i < 1024; i += 256) {
                int r = i >> 3, cc = i & 7;
                uint32_t sw = (uint32_t)(r * 128) + (uint32_t)((cc ^ (r & 7)) << 4);
                size_t goA = ((size_t)(bm + r) << 11) + kcb + (cc << 4);
                size_t goW = ((size_t)(bn + r) << 11) + kcb + (cc << 4);
                CP_ASYNC16(nbuf + sw,          (const char*)Ahi + goA);
                CP_ASYNC16(nbuf + OFF_AL + sw, (const char*)Alo + goA);
                CP_ASYNC16(nbuf + OFF_WH + sw, (const char*)Whi + goW);
                CP_ASYNC16(nbuf + OFF_WL + sw, (const char*)Wlo + goW);
            }
            CP_COMMIT();
            CP_WAIT1();
        } else {
            CP_WAIT0();
        }
        __syncthreads();

        uint32_t bufoff = sb + (c & 1) * BUF_BYTES;
#pragma unroll
        for (int j = 0; j < 4; j++) {
            uint32_t ah[4][4], al[4][4], bh[2][4], bl[2][4];
#pragma unroll
            for (int i = 0; i < 4; i++) {
                uint32_t ad = bufoff + aBase[i] + (uint32_t)(((2 * j + ca) ^ sub) << 4);
                LDSM_X4(ah[i][0], ah[i][1], ah[i][2], ah[i][3], ad);
                LDSM_X4(al[i][0], al[i][1], al[i][2], al[i][3], ad + OFF_AL);
            }
#pragma unroll
            for (int p = 0; p < 2; p++) {
                uint32_t bd = bufoff + bBase[p] + (uint32_t)(((2 * j + cb) ^ sub) << 4);
                LDSM_X4(bh[p][0], bh[p][1], bh[p][2], bh[p][3], bd + OFF_WH);
                LDSM_X4(bl[p][0], bl[p][1], bl[p][2], bl[p][3], bd + OFF_WL);
            }
#pragma unroll
            for (int i = 0; i < 4; i++) {
#pragma unroll
                for (int jn = 0; jn < 4; jn++) {
                    int p = jn >> 1, q = (jn & 1) * 2;
                    MMA16816(acc[i][jn], ah[i], bh[p][q], bh[p][q + 1]);
                    MMA16816(acc[i][jn], ah[i], bl[p][q], bl[p][q + 1]);
                    MMA16816(acc[i][jn], al[i], bh[p][q], bh[p][q + 1]);
                }
            }
        }
        __syncthreads();
    }

    int lr = lid >> 2, lc = (lid & 3) * 2;
#pragma unroll
    for (int i = 0; i < 4; i++) {
#pragma unroll
        for (int jn = 0; jn < 4; jn++) {
            int row = bm + warp_row + i * 16 + lr;
            int colL = warp_col + jn * 8 + lc;
            int col = bn + colL;
            float b0 = bias_s[colL], b1 = bias_s[colL + 1];
            *(float2*)(Cf + (size_t)row * GN + col) =
                make_float2(acc[i][jn][0] + b0, acc[i][jn][1] + b1);
            *(float2*)(Cf + (size_t)(row + 8) * GN + col) =
                make_float2(acc[i][jn][2] + b0, acc[i][jn][3] + b1);
        }
    }
}

// ---------------- type inference v3: warp-per-token, all weights in smem ----------------
#define TK_SMEM ((NTt*Hh + NTt*HDd + 16*HDd + 2*HDd*65) * 4)

__global__ __launch_bounds__(512)
void type_kernel3(const float* __restrict__ x, const float* __restrict__ Wti,
                  const float* __restrict__ bti, const float* __restrict__ temb,
                  const float* __restrict__ Wqt, const float* __restrict__ bqt,
                  const float* __restrict__ Wkt, const float* __restrict__ bkt,
                  float* __restrict__ tl_out, float* __restrict__ qt,
                  __nv_bfloat16* __restrict__ kthi, __nv_bfloat16* __restrict__ ktlo)
{
    extern __shared__ float smf[];
    float* sWti  = smf;
    float* stemb = sWti + NTt * Hh;
    float* slat  = stemb + NTt * HDd;
    float* sWqt  = slat + 16 * HDd;
    float* sWkt  = sWqt + HDd * 65;

    int tid = threadIdx.x, wid = tid >> 5, lid = tid & 31;
    for (int i = tid; i < NTt * Hh; i += 512) sWti[i] = Wti[i];
    for (int i = tid; i < NTt * HDd; i += 512) stemb[i] = temb[i];
    for (int i = tid; i < HDd * HDd; i += 512) {
        int r = i >> 6, c = i & 63;
        sWqt[r * 65 + c] = Wqt[i];
        sWkt[r * 65 + c] = Wkt[i];
    }
    __syncthreads();

    int tok = blockIdx.x * 16 + wid;
    const float* xr = x + (size_t)tok * Hh;
    float xv[32];
#pragma unroll
    for (int j = 0; j < 32; j++) xv[j] = xr[lid + 32 * j];

    float lg[NTt];
#pragma unroll
    for (int t = 0; t < NTt; t++) {
        float s = 0.f;
#pragma unroll
        for (int j = 0; j < 32; j++) s += xv[j] * sWti[t * Hh + lid + 32 * j];
        s += __shfl_xor_sync(0xffffffffu, s, 16);
        s += __shfl_xor_sync(0xffffffffu, s, 8);
        s += __shfl_xor_sync(0xffffffffu, s, 4);
        s += __shfl_xor_sync(0xffffffffu, s, 2);
        s += __shfl_xor_sync(0xffffffffu, s, 1);
        lg[t] = s + bti[t];
    }
    if (lid == 0) {
        float* tl = tl_out + (size_t)tok * NTt;
#pragma unroll
        for (int t = 0; t < NTt; t++) tl[t] = lg[t];
    }
    float mx = lg[0];
#pragma unroll
    for (int t = 1; t < NTt; t++) mx = fmaxf(mx, lg[t]);
    float e[NTt], se = 0.f;
#pragma unroll
    for (int t = 0; t < NTt; t++) { e[t] = expf(lg[t] - mx); se += e[t]; }
    float inv = 1.f / se;

    float la0 = 0.f, la1 = 0.f;
#pragma unroll
    for (int t = 0; t < NTt; t++) {
        float p = e[t] * inv;
        la0 += p * stemb[t * HDd + lid];
        la1 += p * stemb[t * HDd + lid + 32];
    }
    slat[wid * HDd + lid] = la0;
    slat[wid * HDd + lid + 32] = la1;
    __syncwarp();

#pragma unroll
    for (int rep = 0; rep < 2; rep++) {
        int d = lid + rep * 32;
        float a = bqt[d], c = bkt[d];
        const float* wq = sWqt + d * 65;
        const float* wk = sWkt + d * 65;
        const float* la = slat + wid * HDd;
#pragma unroll
        for (int e2 = 0; e2 < HDd; e2++) {
            float lv = la[e2];
            a += lv * wq[e2];
            c += lv * wk[e2];
        }
        qt[(size_t)tok * HDd + d] = a;
        __nv_bfloat16 hc = __float2bfloat16(c);
        kthi[(size_t)tok * HDd + d] = hc;
        ktlo[(size_t)tok * HDd + d] = __float2bfloat16(c - __bfloat162float(hc));
    }
}

// ---------------- qtW (pre-scaled by 1/8, exact) ----------------
__global__ __launch_bounds__(256)
void qtw_kernel(const float* __restrict__ qt, const float* __restrict__ Wb,
                __nv_bfloat16* __restrict__ qwhi, __nv_bfloat16* __restrict__ qwlo)
{
    __shared__ float Qs[64][65];
    __shared__ float Ws[64][65];
    int h = blockIdx.y;
    int t0 = blockIdx.x * 64;
    int tid = threadIdx.x;
    for (int i = tid; i < 4096; i += 256) {
        int r = i >> 6, c = i & 63;
        Qs[r][c] = qt[(size_t)(t0 + r) * HDd + c];
        Ws[r][c] = Wb[(size_t)h * 4096 + i];
    }
    __syncthreads();
    int tx = tid & 15, ty = tid >> 4;
    float acc[4][4];
#pragma unroll
    for (int i = 0; i < 4; i++)
#pragma unroll
        for (int j = 0; j < 4; j++) acc[i][j] = 0.f;
#pragma unroll 4
    for (int d = 0; d < 64; d++) {
        float a[4], b[4];
#pragma unroll
        for (int i = 0; i < 4; i++) a[i] = Qs[ty * 4 + i][d];
#pragma unroll
        for (int j = 0; j < 4; j++) b[j] = Ws[d][tx * 4 + j];
#pragma unroll
        for (int i = 0; i < 4; i++)
#pragma unroll
            for (int j = 0; j < 4; j++) acc[i][j] += a[i] * b[j];
    }
#pragma unroll
    for (int i = 0; i < 4; i++) {
        int tok = t0 + ty * 4 + i;
        int b = tok >> 11;
        int qq = tok & 2047;
        size_t base = (((size_t)(b * NHh + h)) * Ss + qq) * HDd + tx * 4;
        uint32_t h0, l0, h1, l1;
        split2(acc[i][0] * SCALE, acc[i][1] * SCALE, h0, l0);
        split2(acc[i][2] * SCALE, acc[i][3] * SCALE, h1, l1);
        uint2 hv = make_uint2(h0, h1), lv = make_uint2(l0, l1);
        *(uint2*)(qwhi + base) = hv;
        *(uint2*)(qwlo + base) = lv;
    }
}

// ================= HMMA flash attention v5 (unchanged from round 12) =================
#define AKV 16512
#define ATT_QREG 24576
#define ATT_SMEM (ATT_QREG + 2*AKV)   /* 57600 */
#define NKT (Ss/32)

__device__ __forceinline__ void att_load_kv(uint32_t dst, int b, int h, int k0, int tid,
    const __half* kf, const __nv_bfloat16* kthi, const __nv_bfloat16* ktlo,
    const __half* vf, const int* mask)
{
#pragma unroll
    for (int i = tid; i < 256; i += 128) {
        int r = i >> 3, c = i & 7;
        uint32_t sw = (uint32_t)(r * 128) + (uint32_t)((c ^ (r & 7)) << 4);
        size_t gk = ((size_t)(b * Ss + k0 + r)) * 2048 + h * 128 + (c << 4);
        size_t gt = ((size_t)(b * Ss + k0 + r)) * 128 + (c << 4);
        CP_ASYNC16(dst + sw,          (const char*)kf + gk);
        CP_ASYNC16(dst + 4096 + sw,   (const char*)kthi + gt);
        CP_ASYNC16(dst + 8192 + sw,   (const char*)ktlo + gt);
        CP_ASYNC16(dst + 12288 + sw,  (const char*)vf + gk);
    }
    if (tid < 8)
        CP_ASYNC16(dst + 16384 + tid * 16, (const char*)mask + ((size_t)(b * Ss + k0)) * 4 + tid * 16);
}

__global__ __launch_bounds__(128, 3)
void attn_hmma(const __half* __restrict__ qf, const __half* __restrict__ kf,
               const __half* __restrict__ vf,
               const __nv_bfloat16* __restrict__ kthi, const __nv_bfloat16* __restrict__ ktlo,
               const __nv_bfloat16* __restrict__ qwhi, const __nv_bfloat16* __restrict__ qwlo,
               const int* __restrict__ mask, float* __restrict__ unif,
               __nv_bfloat16* __restrict__ ohi, __nv_bfloat16* __restrict__ olo)
{
    extern __shared__ char sm_[];
    uint32_t sb = smem_u32(sm_);
    int tid = threadIdx.x, wid = tid >> 5, lid = tid & 31;
    int b = blockIdx.z, h = blockIdx.y, q0 = blockIdx.x * 64;
    const float NEGINF = __int_as_float(0xff800000);

#pragma unroll
    for (int i = tid; i < 512; i += 128) {
        int r = i >> 3, c = i & 7;
        uint32_t sw = (uint32_t)(r * 128) + (uint32_t)((c ^ (r & 7)) << 4);
        size_t gq = ((size_t)(b * Ss + q0 + r)) * 2048 + h * 128 + (c << 4);
        size_t gw = (((size_t)(b * NHh + h)) * Ss + q0 + r) * 128 + (c << 4);
        CP_ASYNC16(sb + sw,          (const char*)qf + gq);
        CP_ASYNC16(sb + 8192 + sw,   (const char*)qwhi + gw);
        CP_ASYNC16(sb + 16384 + sw,  (const char*)qwlo + gw);
    }
    att_load_kv(sb + ATT_QREG, b, h, 0, tid, kf, kthi, ktlo, vf, mask);
    CP_COMMIT();

    int sub = lid & 7;
    int gA1 = (lid >> 3) & 1, ca = (lid >> 4) & 1;
    int gB2 = (lid >> 4) & 1, cb = (lid >> 3) & 1;
    int arow = wid * 16 + gA1 * 8 + sub;
    uint32_t aoffQ[4];
#pragma unroll
    for (int j = 0; j < 4; j++)
        aoffQ[j] = (uint32_t)(arow * 128) + (uint32_t)(((2 * j + ca) ^ sub) << 4);

    uint32_t qfr[4][4];
    float out[32], sv[16], su[16];
    float lsum0 = 0.f, lsum1 = 0.f;
#pragma unroll
    for (int i = 0; i < 32; i++) out[i] = 0.f;

    int row0 = q0 + wid * 16 + (lid >> 2);
    int mcol = 2 * (lid & 3);

    for (int kt = 0; kt < NKT; kt++) {
        if (kt + 1 < NKT) {
            att_load_kv(sb + ATT_QREG + ((kt + 1) & 1) * AKV, b, h, (kt + 1) * 32, tid,
                        kf, kthi, ktlo, vf, mask);
            CP_COMMIT();
            CP_WAIT1();
        } else {
            CP_WAIT0();
        }
        __syncthreads();

        if (kt == 0) {
#pragma unroll
            for (int j = 0; j < 4; j++)
                LDSM_X4(qfr[j][0], qfr[j][1], qfr[j][2], qfr[j][3], sb + aoffQ[j]);
        }

        uint32_t cbuf = sb + ATT_QREG + (kt & 1) * AKV;
        int k0 = kt * 32;
#pragma unroll
        for (int i = 0; i < 16; i++) { sv[i] = 0.f; su[i] = 0.f; }

#pragma unroll
        for (int j = 0; j < 4; j++) {
            uint32_t bh[8];
#pragma unroll
            for (int p = 0; p < 2; p++) {
                uint32_t bo = (uint32_t)((p * 16 + gB2 * 8 + sub) * 128)
                            + (uint32_t)(((2 * j + cb) ^ sub) << 4);
                LDSM_X4(bh[4*p], bh[4*p+1], bh[4*p+2], bh[4*p+3], cbuf + bo);
            }
#pragma unroll
            for (int jn = 0; jn < 4; jn++) {
                int bi = (jn >> 1) * 4 + (jn & 1) * 2;
                MMAF16(sv + 4*jn, qfr[j], bh[bi], bh[bi+1]);
            }
        }
#pragma unroll
        for (int j = 0; j < 4; j++) {
            uint32_t aw_h[4], aw_l[4], bh[8], bl[8];
            LDSM_X4(aw_h[0], aw_h[1], aw_h[2], aw_h[3], sb + 8192 + aoffQ[j]);
            LDSM_X4(aw_l[0], aw_l[1], aw_l[2], aw_l[3], sb + 16384 + aoffQ[j]);
#pragma unroll
            for (int p = 0; p < 2; p++) {
                uint32_t bo = (uint32_t)((p * 16 + gB2 * 8 + sub) * 128)
                            + (uint32_t)(((2 * j + cb) ^ sub) << 4);
                LDSM_X4(bh[4*p], bh[4*p+1], bh[4*p+2], bh[4*p+3], cbuf + 4096 + bo);
                LDSM_X4(bl[4*p], bl[4*p+1], bl[4*p+2], bl[4*p+3], cbuf + 8192 + bo);
            }
#pragma unroll
            for (int jn = 0; jn < 4; jn++) {
                int bi = (jn >> 1) * 4 + (jn & 1) * 2;
                MMA16816(su + 4*jn, aw_h, bh[bi], bh[bi+1]);
                MMA16816(su + 4*jn, aw_h, bl[bi], bl[bi+1]);
                MMA16816(su + 4*jn, aw_l, bh[bi], bh[bi+1]);
            }
        }

        const char* mbuf = sm_ + ATT_QREG + (kt & 1) * AKV + 16384;
        uint32_t pa[2][4];
#pragma unroll
        for (int jn = 0; jn < 4; jn++) {
            int colL = jn * 8 + mcol;
            size_t ub = (((size_t)(b * NHh + h)) * Ss + row0) * Ss + k0 + colL;
            *(float2*)(unif + ub)          = make_float2(su[4*jn],   su[4*jn+1]);
            *(float2*)(unif + ub + 8 * Ss) = make_float2(su[4*jn+2], su[4*jn+3]);
            int2 mk = *(const int2*)(mbuf + colL * 4);
            float s0 = mk.x ? sv[4*jn]   : NEGINF;
            float s1 = mk.y ? sv[4*jn+1] : NEGINF;
            float s2 = mk.x ? sv[4*jn+2] : NEGINF;
            float s3 = mk.y ? sv[4*jn+3] : NEGINF;
            float g0 = __fdividef(1.f, 1.f + __expf(-su[4*jn]))   + 1e-6f;
            float g1 = __fdividef(1.f, 1.f + __expf(-su[4*jn+1])) + 1e-6f;
            float g2 = __fdividef(1.f, 1.f + __expf(-su[4*jn+2])) + 1e-6f;
            float g3 = __fdividef(1.f, 1.f + __expf(-su[4*jn+3])) + 1e-6f;
            float p0 = __expf(s0) * g0;
            float p1 = __expf(s1) * g1;
            float p2 = __expf(s2) * g2;
            float p3 = __expf(s3) * g3;
            lsum0 += p0 + p1;
            lsum1 += p2 + p3;
            int t = jn >> 1, o = (jn & 1) * 2;
            pa[t][o]     = packh2(p0, p1);
            pa[t][o + 1] = packh2(p2, p3);
        }

#pragma unroll
        for (int t = 0; t < 2; t++) {
#pragma unroll
            for (int g = 0; g < 4; g++) {
                uint32_t vro = (uint32_t)((t * 16 + (lid & 15)) * 128)
                             + (uint32_t)(((2 * g + ((lid >> 4) & 1)) ^ (lid & 7)) << 4);
                uint32_t vh[4];
                LDSM_X4_T(vh[0], vh[1], vh[2], vh[3], cbuf + 12288 + vro);
                MMAF16(out + 4*(2*g),   pa[t], vh[0], vh[1]);
                MMAF16(out + 4*(2*g+1), pa[t], vh[2], vh[3]);
            }
        }
        __syncthreads();
    }

    lsum0 += __shfl_xor_sync(0xffffffffu, lsum0, 1);
    lsum0 += __shfl_xor_sync(0xffffffffu, lsum0, 2);
    lsum1 += __shfl_xor_sync(0xffffffffu, lsum1, 1);
    lsum1 += __shfl_xor_sync(0xffffffffu, lsum1, 2);
    float i0 = 1.f / lsum0, i1 = 1.f / lsum1;
    size_t r0g = (size_t)(b * Ss + row0);
#pragma unroll
    for (int dn = 0; dn < 8; dn++) {
        int col = h * 64 + dn * 8 + mcol;
        uint32_t h0, l0, h1, l1;
        split2(out[4*dn] * i0,   out[4*dn+1] * i0, h0, l0);
        split2(out[4*dn+2] * i1, out[4*dn+3] * i1, h1, l1);
        *(uint32_t*)(ohi + r0g * Hh + col)       = h0;
        *(uint32_t*)(olo + r0g * Hh + col)       = l0;
        *(uint32_t*)(ohi + (r0g + 8) * Hh + col) = h1;
        *(uint32_t*)(olo + (r0g + 8) * Hh + col) = l1;
    }
}

// ---------------- launch ----------------
extern "C" void kernel_launch(void* const* d_in, const int* in_sizes, int n_in,
                              void* d_out, int out_size)
{
    (void)in_sizes; (void)n_in; (void)out_size;
    const float* x    = (const float*)d_in[0];
    const int*   mask = (const int*)  d_in[1];
    const float* Wq   = (const float*)d_in[2];
    const float* bq   = (const float*)d_in[3];
    const float* Wk   = (const float*)d_in[4];
    const float* bk   = (const float*)d_in[5];
    const float* Wv   = (const float*)d_in[6];
    const float* bv   = (const float*)d_in[7];
    const float* Wo   = (const float*)d_in[8];
    const float* bo   = (const float*)d_in[9];
    const float* Wti  = (const float*)d_in[10];
    const float* bti  = (const float*)d_in[11];
    const float* temb = (const float*)d_in[12];
    const float* Wqt  = (const float*)d_in[13];
    const float* bqt  = (const float*)d_in[14];
    const float* Wkt  = (const float*)d_in[15];
    const float* bkt  = (const float*)d_in[16];
    const float* Wbil = (const float*)d_in[17];

    float* out      = (float*)d_out;
    float* out_y    = out;
    float* out_tl   = out + (size_t)TOKS * Hh;
    float* out_unif = out_tl + (size_t)TOKS * NTt;

    float* qt;
    __nv_bfloat16 *ohi, *olo, *whi, *wlo, *kth, *ktl, *qwh, *qwl;
    __half *xf, *wf, *qfp, *kfp, *vfp;
    cudaGetSymbolAddress((void**)&qt,   g_qt);
    cudaGetSymbolAddress((void**)&xf,   g_xf);
    cudaGetSymbolAddress((void**)&wf,   g_wf);
    cudaGetSymbolAddress((void**)&ohi,  g_xhi);
    cudaGetSymbolAddress((void**)&olo,  g_xlo);
    cudaGetSymbolAddress((void**)&whi,  g_whi);
    cudaGetSymbolAddress((void**)&wlo,  g_wlo);
    cudaGetSymbolAddress((void**)&qfp,  g_qf);
    cudaGetSymbolAddress((void**)&kfp,  g_kf);
    cudaGetSymbolAddress((void**)&vfp,  g_vf);
    cudaGetSymbolAddress((void**)&kth,  g_kthi);
    cudaGetSymbolAddress((void**)&ktl,  g_ktlo);
    cudaGetSymbolAddress((void**)&qwh,  g_qwhi);
    cudaGetSymbolAddress((void**)&qwl,  g_qwlo);

    const size_t WSZ = (size_t)Hh * Hh;
    cvt_f16<<<(TOKS * Hh / 4 + 1023) / 1024, 256>>>((const float4*)x, xf, TOKS * Hh / 4);
    cvt_f16_w3<<<dim3((WSZ / 4 + 1023) / 1024, 3), 256>>>(
        (const float4*)Wq, (const float4*)Wk, (const float4*)Wv, wf);
    cvt_split<<<(WSZ / 4 + 1023) / 1024, 256>>>((const float4*)Wo,
        (__nv_bfloat162*)whi, (__nv_bfloat162*)wlo, WSZ / 4);

    cudaFuncSetAttribute(gemm_qkv_f16, cudaFuncAttributeMaxDynamicSharedMemorySize, GF_SMEM);
    cudaFuncSetAttribute(gemm_o,       cudaFuncAttributeMaxDynamicSharedMemorySize, GEMM_SMEM);
    gemm_qkv_f16<<<dim3(GN / 128, TOKS / 128, 3), 256, GF_SMEM>>>(
        xf, wf, bq, bk, bv, qfp, kfp, vfp);

    cudaFuncSetAttribute(type_kernel3, cudaFuncAttributeMaxDynamicSharedMemorySize, TK_SMEM);
    type_kernel3<<<TOKS / 16, 512, TK_SMEM>>>(x, Wti, bti, temb, Wqt, bqt, Wkt, bkt,
                                              out_tl, qt, kth, ktl);

    qtw_kernel<<<dim3(TOKS / 64, NHh), 256>>>(qt, Wbil, qwh, qwl);

    cudaFuncSetAttribute(attn_hmma, cudaFuncAttributeMaxDynamicSharedMemorySize, ATT_SMEM);
    attn_hmma<<<dim3(Ss / 64, NHh, Bb), 128, ATT_SMEM>>>(qfp, kfp, vfp,
        kth, ktl, qwh, qwl, mask, out_unif, ohi, olo);

    gemm_o<<<dim3(GN / 128, TOKS / 128), 256, GEMM_SMEM>>>(ohi, olo, whi, wlo, bo, out_y);
}

// round 15
// speedup vs baseline: 1.1057x; 1.1057x over previous
#include <cuda_runtime.h>
#include <cuda_bf16.h>
#include <cuda_fp16.h>
#include <cstdint>
#include <cstddef>

#define Bb 2
#define Ss 2048
#define Hh 1024
#define NHh 16
#define HDd 64
#define NTt 5
#define TOKS (Bb*Ss)          /* 4096 */
#define SCALE 0.125f          /* 1/sqrt(64) */

// ---------------- scratch (static device globals; no allocation) ----------------
__device__ float g_qt[(size_t)TOKS*HDd];
__device__ __half g_xf[(size_t)TOKS*Hh];         /* x fp16, later reused as attn-out fp16 */
__device__ __half g_wf[(size_t)4*Hh*Hh];         /* Wq,Wk,Wv,Wo fp16 */
__device__ __half g_qf[(size_t)TOKS*Hh];
__device__ __half g_kf[(size_t)TOKS*Hh];
__device__ __half g_vf[(size_t)TOKS*Hh];
__device__ __nv_bfloat16 g_kthi[(size_t)TOKS*HDd];
__device__ __nv_bfloat16 g_ktlo[(size_t)TOKS*HDd];
__device__ __nv_bfloat16 g_qwhi[(size_t)Bb*NHh*Ss*HDd];
__device__ __nv_bfloat16 g_qwlo[(size_t)Bb*NHh*Ss*HDd];

// ================= low-level helpers (all plain sm_80+ features) =================
__device__ __forceinline__ uint32_t smem_u32(const void* p) {
    uint32_t a;
    asm("{ .reg .u64 t; cvta.to.shared.u64 t, %1; cvt.u32.u64 %0, t; }" : "=r"(a) : "l"(p));
    return a;
}
#define CP_ASYNC16(saddr, gaddr) \
    asm volatile("cp.async.cg.shared.global [%0], [%1], 16;" :: "r"(saddr), "l"(gaddr))
#define CP_COMMIT() asm volatile("cp.async.commit_group;" ::: "memory")
#define CP_WAIT1()  asm volatile("cp.async.wait_group 1;" ::: "memory")
#define CP_WAIT0()  asm volatile("cp.async.wait_group 0;" ::: "memory")
#define LDSM_X4(r0, r1, r2, r3, addr) \
    asm volatile("ldmatrix.sync.aligned.m8n8.x4.shared.b16 {%0,%1,%2,%3}, [%4];" \
        : "=r"(r0), "=r"(r1), "=r"(r2), "=r"(r3) : "r"(addr))
#define LDSM_X4_T(r0, r1, r2, r3, addr) \
    asm volatile("ldmatrix.sync.aligned.m8n8.x4.trans.shared.b16 {%0,%1,%2,%3}, [%4];" \
        : "=r"(r0), "=r"(r1), "=r"(r2), "=r"(r3) : "r"(addr))
#define MMA16816(c, a, b0, b1) \
    asm volatile("mma.sync.aligned.m16n8k16.row.col.f32.bf16.bf16.f32 " \
        "{%0,%1,%2,%3}, {%4,%5,%6,%7}, {%8,%9}, {%0,%1,%2,%3};" \
        : "+f"((c)[0]), "+f"((c)[1]), "+f"((c)[2]), "+f"((c)[3]) \
        : "r"((a)[0]), "r"((a)[1]), "r"((a)[2]), "r"((a)[3]), "r"(b0), "r"(b1))
#define MMAF16(c, a, b0, b1) \
    asm volatile("mma.sync.aligned.m16n8k16.row.col.f32.f16.f16.f32 " \
        "{%0,%1,%2,%3}, {%4,%5,%6,%7}, {%8,%9}, {%0,%1,%2,%3};" \
        : "+f"((c)[0]), "+f"((c)[1]), "+f"((c)[2]), "+f"((c)[3]) \
        : "r"((a)[0]), "r"((a)[1]), "r"((a)[2]), "r"((a)[3]), "r"(b0), "r"(b1))

__device__ __forceinline__ void split2(float x, float y, uint32_t& hi, uint32_t& lo) {
    __nv_bfloat16 hx = __float2bfloat16(x), hy = __float2bfloat16(y);
    __nv_bfloat16 lx = __float2bfloat16(x - __bfloat162float(hx));
    __nv_bfloat16 ly = __float2bfloat16(y - __bfloat162float(hy));
    __nv_bfloat162 h2(hx, hy), l2(lx, ly);
    hi = *(uint32_t*)&h2; lo = *(uint32_t*)&l2;
}
__device__ __forceinline__ uint32_t packh2(float x, float y) {
    __half2 h = __floats2half2_rn(x, y);
    return *(uint32_t*)&h;
}

// ================= conversions =================
// fp32 -> fp16 single (x), 4 float4 per thread
__global__ __launch_bounds__(256)
void cvt_f16(const float4* __restrict__ in, __half* __restrict__ out, int n4)
{
    int base = blockIdx.x * 1024 + threadIdx.x;
    float4 f[4];
    int idx[4];
#pragma unroll
    for (int u = 0; u < 4; u++) {
        idx[u] = base + u * 256;
        if (idx[u] < n4) f[u] = in[idx[u]];
    }
#pragma unroll
    for (int u = 0; u < 4; u++) {
        if (idx[u] >= n4) continue;
        uint2 o;
        o.x = packh2(f[u].x, f[u].y);
        o.y = packh2(f[u].z, f[u].w);
        *(uint2*)(out + (size_t)idx[u] * 4) = o;
    }
}

// Wq/Wk/Wv/Wo -> fp16 in one launch (grid.y selects)
__global__ __launch_bounds__(256)
void cvt_f16_w4(const float4* __restrict__ W0, const float4* __restrict__ W1,
                const float4* __restrict__ W2, const float4* __restrict__ W3,
                __half* __restrict__ out)
{
    const int n4 = Hh * Hh / 4;
    int z = blockIdx.y;
    const float4* in = (z == 0) ? W0 : (z == 1) ? W1 : (z == 2) ? W2 : W3;
    int base = blockIdx.x * 1024 + threadIdx.x;
    float4 f[4];
    int idx[4];
#pragma unroll
    for (int u = 0; u < 4; u++) {
        idx[u] = base + u * 256;
        if (idx[u] < n4) f[u] = in[idx[u]];
    }
    size_t zb = (size_t)z * Hh * Hh;
#pragma unroll
    for (int u = 0; u < 4; u++) {
        if (idx[u] >= n4) continue;
        uint2 o;
        o.x = packh2(f[u].x, f[u].y);
        o.y = packh2(f[u].z, f[u].w);
        *(uint2*)(out + zb + (size_t)idx[u] * 4) = o;
    }
}

// ================= fp16 single-term GEMM body: C = A @ W^T + b =================
#define GN 1024
#define GF_BUF 32768
#define GF_SMEM (2*GF_BUF + 512)

__device__ __forceinline__ void gemm_f16_body(
    const __half* __restrict__ Af, const __half* __restrict__ Wf,
    const float* __restrict__ bias, float oscale,
    __half* __restrict__ Ch, float* __restrict__ Cf,
    char* sm_, int bm, int bn)
{
    uint32_t sb = smem_u32(sm_);
    float* bias_s = (float*)(sm_ + 2 * GF_BUF);
    int tid = threadIdx.x, wid = tid >> 5, lid = tid & 31;
    if (tid < 128) bias_s[tid] = bias[bn + tid];

    int warp_row = (wid & 1) * 64;
    int warp_col = (wid >> 1) * 32;
    int sub = lid & 7;
    int gA1 = (lid >> 3) & 1, ca = (lid >> 4) & 1;
    int gB2 = (lid >> 4) & 1, cb = (lid >> 3) & 1;

    uint32_t aBase[4], bBase[2];
#pragma unroll
    for (int i = 0; i < 4; i++)
        aBase[i] = (uint32_t)((warp_row + i * 16 + gA1 * 8 + sub) * 128);
#pragma unroll
    for (int p = 0; p < 2; p++)
        bBase[p] = (uint32_t)((warp_col + p * 16 + gB2 * 8 + sub) * 128);

    float acc[4][4][4];
#pragma unroll
    for (int i = 0; i < 4; i++)
#pragma unroll
        for (int jn = 0; jn < 4; jn++)
#pragma unroll
            for (int r = 0; r < 4; r++) acc[i][jn][r] = 0.f;

#pragma unroll
    for (int i = tid; i < 1024; i += 256) {
        int r = i >> 3, c = i & 7;
        uint32_t sw = (uint32_t)(r * 128) + (uint32_t)((c ^ (r & 7)) << 4);
        CP_ASYNC16(sb + sw,           (const char*)Af + (((size_t)(bm + r)) << 11) + (c << 4));
        CP_ASYNC16(sb + 16384 + sw,   (const char*)Wf + (((size_t)(bn + r)) << 11) + (c << 4));
    }
    CP_COMMIT();

    for (int c = 0; c < 16; c++) {
        if (c + 1 < 16) {
            uint32_t nbuf = sb + ((c + 1) & 1) * GF_BUF;
            int kcb = (c + 1) * 128;
#pragma unroll
            for (int i = tid; i < 1024; i += 256) {
                int r = i >> 3, cc = i & 7;
                uint32_t sw = (uint32_t)(r * 128) + (uint32_t)((cc ^ (r & 7)) << 4);
                CP_ASYNC16(nbuf + sw,         (const char*)Af + (((size_t)(bm + r)) << 11) + kcb + (cc << 4));
                CP_ASYNC16(nbuf + 16384 + sw, (const char*)Wf + (((size_t)(bn + r)) << 11) + kcb + (cc << 4));
            }
            CP_COMMIT();
            CP_WAIT1();
        } else {
            CP_WAIT0();
        }
        __syncthreads();

        uint32_t bufoff = sb + (c & 1) * GF_BUF;
#pragma unroll
        for (int j = 0; j < 4; j++) {
            uint32_t ah[4][4], bh[2][4];
#pragma unroll
            for (int i = 0; i < 4; i++) {
                uint32_t ad = bufoff + aBase[i] + (uint32_t)(((2 * j + ca) ^ sub) << 4);
                LDSM_X4(ah[i][0], ah[i][1], ah[i][2], ah[i][3], ad);
            }
#pragma unroll
            for (int p = 0; p < 2; p++) {
                uint32_t bd = bufoff + 16384 + bBase[p] + (uint32_t)(((2 * j + cb) ^ sub) << 4);
                LDSM_X4(bh[p][0], bh[p][1], bh[p][2], bh[p][3], bd);
            }
#pragma unroll
            for (int i = 0; i < 4; i++) {
#pragma unroll
                for (int jn = 0; jn < 4; jn++) {
                    int p = jn >> 1, q = (jn & 1) * 2;
                    MMAF16(acc[i][jn], ah[i], bh[p][q], bh[p][q + 1]);
                }
            }
        }
        __syncthreads();
    }

    int lr = lid >> 2, lc = (lid & 3) * 2;
#pragma unroll
    for (int i = 0; i < 4; i++) {
#pragma unroll
        for (int jn = 0; jn < 4; jn++) {
            int row = bm + warp_row + i * 16 + lr;
            int colL = warp_col + jn * 8 + lc;
            int col = bn + colL;
            float b0 = bias_s[colL], b1 = bias_s[colL + 1];
            float v00 = (acc[i][jn][0] + b0) * oscale, v01 = (acc[i][jn][1] + b1) * oscale;
            float v10 = (acc[i][jn][2] + b0) * oscale, v11 = (acc[i][jn][3] + b1) * oscale;
            if (Ch) {
                *(uint32_t*)(Ch + (size_t)row * GN + col)       = packh2(v00, v01);
                *(uint32_t*)(Ch + (size_t)(row + 8) * GN + col) = packh2(v10, v11);
            } else {
                *(float2*)(Cf + (size_t)row * GN + col)       = make_float2(v00, v01);
                *(float2*)(Cf + (size_t)(row + 8) * GN + col) = make_float2(v10, v11);
            }
        }
    }
}

// fused Q/K/V projection: grid.z selects. Outputs fp16 single. Q pre-scaled by 1/8 (exact).
__global__ __launch_bounds__(256)
void gemm_qkv_f16(const __half* __restrict__ xf, const __half* __restrict__ wf,
                  const float* __restrict__ bq, const float* __restrict__ bk,
                  const float* __restrict__ bv,
                  __half* __restrict__ qf, __half* __restrict__ kf, __half* __restrict__ vf)
{
    extern __shared__ char sm_[];
    int z = blockIdx.z;
    const __half* Wf = wf + (size_t)z * Hh * Hh;
    const float* bias = (z == 0) ? bq : (z == 1) ? bk : bv;
    __half* Ch = (z == 0) ? qf : (z == 1) ? kf : vf;
    float oscale = (z == 0) ? SCALE : 1.f;
    gemm_f16_body(xf, Wf, bias, oscale, Ch, nullptr, sm_,
                  blockIdx.y * 128, blockIdx.x * 128);
}

// O projection: fp16 inputs, fp32 output
__global__ __launch_bounds__(256)
void gemm_o_f16(const __half* __restrict__ of, const __half* __restrict__ wf,
                const float* __restrict__ bias, float* __restrict__ Cf)
{
    extern __shared__ char sm_[];
    gemm_f16_body(of, wf + (size_t)3 * Hh * Hh, bias, 1.f, nullptr, Cf, sm_,
                  blockIdx.y * 128, blockIdx.x * 128);
}

// ---------------- type inference v3: warp-per-token, all weights in smem ----------------
#define TK_SMEM ((NTt*Hh + NTt*HDd + 16*HDd + 2*HDd*65) * 4)

__global__ __launch_bounds__(512)
void type_kernel3(const float* __restrict__ x, const float* __restrict__ Wti,
                  const float* __restrict__ bti, const float* __restrict__ temb,
                  const float* __restrict__ Wqt, const float* __restrict__ bqt,
                  const float* __restrict__ Wkt, const float* __restrict__ bkt,
                  float* __restrict__ tl_out, float* __restrict__ qt,
                  __nv_bfloat16* __restrict__ kthi, __nv_bfloat16* __restrict__ ktlo)
{
    extern __shared__ float smf[];
    float* sWti  = smf;
    float* stemb = sWti + NTt * Hh;
    float* slat  = stemb + NTt * HDd;
    float* sWqt  = slat + 16 * HDd;
    float* sWkt  = sWqt + HDd * 65;

    int tid = threadIdx.x, wid = tid >> 5, lid = tid & 31;
    for (int i = tid; i < NTt * Hh; i += 512) sWti[i] = Wti[i];
    for (int i = tid; i < NTt * HDd; i += 512) stemb[i] = temb[i];
    for (int i = tid; i < HDd * HDd; i += 512) {
        int r = i >> 6, c = i & 63;
        sWqt[r * 65 + c] = Wqt[i];
        sWkt[r * 65 + c] = Wkt[i];
    }
    __syncthreads();

    int tok = blockIdx.x * 16 + wid;
    const float* xr = x + (size_t)tok * Hh;
    float xv[32];
#pragma unroll
    for (int j = 0; j < 32; j++) xv[j] = xr[lid + 32 * j];

    float lg[NTt];
#pragma unroll
    for (int t = 0; t < NTt; t++) {
        float s = 0.f;
#pragma unroll
        for (int j = 0; j < 32; j++) s += xv[j] * sWti[t * Hh + lid + 32 * j];
        s += __shfl_xor_sync(0xffffffffu, s, 16);
        s += __shfl_xor_sync(0xffffffffu, s, 8);
        s += __shfl_xor_sync(0xffffffffu, s, 4);
        s += __shfl_xor_sync(0xffffffffu, s, 2);
        s += __shfl_xor_sync(0xffffffffu, s, 1);
        lg[t] = s + bti[t];
    }
    if (lid == 0) {
        float* tl = tl_out + (size_t)tok * NTt;
#pragma unroll
        for (int t = 0; t < NTt; t++) tl[t] = lg[t];
    }
    float mx = lg[0];
#pragma unroll
    for (int t = 1; t < NTt; t++) mx = fmaxf(mx, lg[t]);
    float e[NTt], se = 0.f;
#pragma unroll
    for (int t = 0; t < NTt; t++) { e[t] = expf(lg[t] - mx); se += e[t]; }
    float inv = 1.f / se;

    float la0 = 0.f, la1 = 0.f;
#pragma unroll
    for (int t = 0; t < NTt; t++) {
        float p = e[t] * inv;
        la0 += p * stemb[t * HDd + lid];
        la1 += p * stemb[t * HDd + lid + 32];
    }
    slat[wid * HDd + lid] = la0;
    slat[wid * HDd + lid + 32] = la1;
    __syncwarp();

#pragma unroll
    for (int rep = 0; rep < 2; rep++) {
        int d = lid + rep * 32;
        float a = bqt[d], c = bkt[d];
        const float* wq = sWqt + d * 65;
        const float* wk = sWkt + d * 65;
        const float* la = slat + wid * HDd;
#pragma unroll
        for (int e2 = 0; e2 < HDd; e2++) {
            float lv = la[e2];
            a += lv * wq[e2];
            c += lv * wk[e2];
        }
        qt[(size_t)tok * HDd + d] = a;
        __nv_bfloat16 hc = __float2bfloat16(c);
        kthi[(size_t)tok * HDd + d] = hc;
        ktlo[(size_t)tok * HDd + d] = __float2bfloat16(c - __bfloat162float(hc));
    }
}

// ---------------- qtW (pre-scaled by 1/8, exact) ----------------
__global__ __launch_bounds__(256)
void qtw_kernel(const float* __restrict__ qt, const float* __restrict__ Wb,
                __nv_bfloat16* __restrict__ qwhi, __nv_bfloat16* __restrict__ qwlo)
{
    __shared__ float Qs[64][65];
    __shared__ float Ws[64][65];
    int h = blockIdx.y;
    int t0 = blockIdx.x * 64;
    int tid = threadIdx.x;
    for (int i = tid; i < 4096; i += 256) {
        int r = i >> 6, c = i & 63;
        Qs[r][c] = qt[(size_t)(t0 + r) * HDd + c];
        Ws[r][c] = Wb[(size_t)h * 4096 + i];
    }
    __syncthreads();
    int tx = tid & 15, ty = tid >> 4;
    float acc[4][4];
#pragma unroll
    for (int i = 0; i < 4; i++)
#pragma unroll
        for (int j = 0; j < 4; j++) acc[i][j] = 0.f;
#pragma unroll 4
    for (int d = 0; d < 64; d++) {
        float a[4], b[4];
#pragma unroll
        for (int i = 0; i < 4; i++) a[i] = Qs[ty * 4 + i][d];
#pragma unroll
        for (int j = 0; j < 4; j++) b[j] = Ws[d][tx * 4 + j];
#pragma unroll
        for (int i = 0; i < 4; i++)
#pragma unroll
            for (int j = 0; j < 4; j++) acc[i][j] += a[i] * b[j];
    }
#pragma unroll
    for (int i = 0; i < 4; i++) {
        int tok = t0 + ty * 4 + i;
        int b = tok >> 11;
        int qq = tok & 2047;
        size_t base = (((size_t)(b * NHh + h)) * Ss + qq) * HDd + tx * 4;
        uint32_t h0, l0, h1, l1;
        split2(acc[i][0] * SCALE, acc[i][1] * SCALE, h0, l0);
        split2(acc[i][2] * SCALE, acc[i][3] * SCALE, h1, l1);
        uint2 hv = make_uint2(h0, h1), lv = make_uint2(l0, l1);
        *(uint2*)(qwhi + base) = hv;
        *(uint2*)(qwlo + base) = lv;
    }
}

// ================= HMMA flash attention v5 (fp16 epilogue) =================
#define AKV 16512
#define ATT_QREG 24576
#define ATT_SMEM (ATT_QREG + 2*AKV)   /* 57600 */
#define NKT (Ss/32)

__device__ __forceinline__ void att_load_kv(uint32_t dst, int b, int h, int k0, int tid,
    const __half* kf, const __nv_bfloat16* kthi, const __nv_bfloat16* ktlo,
    const __half* vf, const int* mask)
{
#pragma unroll
    for (int i = tid; i < 256; i += 128) {
        int r = i >> 3, c = i & 7;
        uint32_t sw = (uint32_t)(r * 128) + (uint32_t)((c ^ (r & 7)) << 4);
        size_t gk = ((size_t)(b * Ss + k0 + r)) * 2048 + h * 128 + (c << 4);
        size_t gt = ((size_t)(b * Ss + k0 + r)) * 128 + (c << 4);
        CP_ASYNC16(dst + sw,          (const char*)kf + gk);
        CP_ASYNC16(dst + 4096 + sw,   (const char*)kthi + gt);
        CP_ASYNC16(dst + 8192 + sw,   (const char*)ktlo + gt);
        CP_ASYNC16(dst + 12288 + sw,  (const char*)vf + gk);
    }
    if (tid < 8)
        CP_ASYNC16(dst + 16384 + tid * 16, (const char*)mask + ((size_t)(b * Ss + k0)) * 4 + tid * 16);
}

__global__ __launch_bounds__(128, 3)
void attn_hmma(const __half* __restrict__ qf, const __half* __restrict__ kf,
               const __half* __restrict__ vf,
               const __nv_bfloat16* __restrict__ kthi, const __nv_bfloat16* __restrict__ ktlo,
               const __nv_bfloat16* __restrict__ qwhi, const __nv_bfloat16* __restrict__ qwlo,
               const int* __restrict__ mask, float* __restrict__ unif,
               __half* __restrict__ of)
{
    extern __shared__ char sm_[];
    uint32_t sb = smem_u32(sm_);
    int tid = threadIdx.x, wid = tid >> 5, lid = tid & 31;
    int b = blockIdx.z, h = blockIdx.y, q0 = blockIdx.x * 64;
    const float NEGINF = __int_as_float(0xff800000);

#pragma unroll
    for (int i = tid; i < 512; i += 128) {
        int r = i >> 3, c = i & 7;
        uint32_t sw = (uint32_t)(r * 128) + (uint32_t)((c ^ (r & 7)) << 4);
        size_t gq = ((size_t)(b * Ss + q0 + r)) * 2048 + h * 128 + (c << 4);
        size_t gw = (((size_t)(b * NHh + h)) * Ss + q0 + r) * 128 + (c << 4);
        CP_ASYNC16(sb + sw,          (const char*)qf + gq);
        CP_ASYNC16(sb + 8192 + sw,   (const char*)qwhi + gw);
        CP_ASYNC16(sb + 16384 + sw,  (const char*)qwlo + gw);
    }
    att_load_kv(sb + ATT_QREG, b, h, 0, tid, kf, kthi, ktlo, vf, mask);
    CP_COMMIT();

    int sub = lid & 7;
    int gA1 = (lid >> 3) & 1, ca = (lid >> 4) & 1;
    int gB2 = (lid >> 4) & 1, cb = (lid >> 3) & 1;
    int arow = wid * 16 + gA1 * 8 + sub;
    uint32_t aoffQ[4];
#pragma unroll
    for (int j = 0; j < 4; j++)
        aoffQ[j] = (uint32_t)(arow * 128) + (uint32_t)(((2 * j + ca) ^ sub) << 4);

    uint32_t qfr[4][4];
    float out[32], sv[16], su[16];
    float lsum0 = 0.f, lsum1 = 0.f;
#pragma unroll
    for (int i = 0; i < 32; i++) out[i] = 0.f;

    int row0 = q0 + wid * 16 + (lid >> 2);
    int mcol = 2 * (lid & 3);

    for (int kt = 0; kt < NKT; kt++) {
        if (kt + 1 < NKT) {
            att_load_kv(sb + ATT_QREG + ((kt + 1) & 1) * AKV, b, h, (kt + 1) * 32, tid,
                        kf, kthi, ktlo, vf, mask);
            CP_COMMIT();
            CP_WAIT1();
        } else {
            CP_WAIT0();
        }
        __syncthreads();

        if (kt == 0) {
#pragma unroll
            for (int j = 0; j < 4; j++)
                LDSM_X4(qfr[j][0], qfr[j][1], qfr[j][2], qfr[j][3], sb + aoffQ[j]);
        }

        uint32_t cbuf = sb + ATT_QREG + (kt & 1) * AKV;
        int k0 = kt * 32;
#pragma unroll
        for (int i = 0; i < 16; i++) { sv[i] = 0.f; su[i] = 0.f; }

#pragma unroll
        for (int j = 0; j < 4; j++) {
            uint32_t bh[8];
#pragma unroll
            for (int p = 0; p < 2; p++) {
                uint32_t bo = (uint32_t)((p * 16 + gB2 * 8 + sub) * 128)
                            + (uint32_t)(((2 * j + cb) ^ sub) << 4);
                LDSM_X4(bh[4*p], bh[4*p+1], bh[4*p+2], bh[4*p+3], cbuf + bo);
            }
#pragma unroll
            for (int jn = 0; jn < 4; jn++) {
                int bi = (jn >> 1) * 4 + (jn & 1) * 2;
                MMAF16(sv + 4*jn, qfr[j], bh[bi], bh[bi+1]);
            }
        }
#pragma unroll
        for (int j = 0; j < 4; j++) {
            uint32_t aw_h[4], aw_l[4], bh[8], bl[8];
            LDSM_X4(aw_h[0], aw_h[1], aw_h[2], aw_h[3], sb + 8192 + aoffQ[j]);
            LDSM_X4(aw_l[0], aw_l[1], aw_l[2], aw_l[3], sb + 16384 + aoffQ[j]);
#pragma unroll
            for (int p = 0; p < 2; p++) {
                uint32_t bo = (uint32_t)((p * 16 + gB2 * 8 + sub) * 128)
                            + (uint32_t)(((2 * j + cb) ^ sub) << 4);
                LDSM_X4(bh[4*p], bh[4*p+1], bh[4*p+2], bh[4*p+3], cbuf + 4096 + bo);
                LDSM_X4(bl[4*p], bl[4*p+1], bl[4*p+2], bl[4*p+3], cbuf + 8192 + bo);
            }
#pragma unroll
            for (int jn = 0; jn < 4; jn++) {
                int bi = (jn >> 1) * 4 + (jn & 1) * 2;
                MMA16816(su + 4*jn, aw_h, bh[bi], bh[bi+1]);
                MMA16816(su + 4*jn, aw_h, bl[bi], bl[bi+1]);
                MMA16816(su + 4*jn, aw_l, bh[bi], bh[bi+1]);
            }
        }

        const char* mbuf = sm_ + ATT_QREG + (kt & 1) * AKV + 16384;
        uint32_t pa[2][4];
#pragma unroll
        for (int jn = 0; jn < 4; jn++) {
            int colL = jn * 8 + mcol;
            size_t ub = (((size_t)(b * NHh + h)) * Ss + row0) * Ss + k0 + colL;
            *(float2*)(unif + ub)          = make_float2(su[4*jn],   su[4*jn+1]);
            *(float2*)(unif + ub + 8 * Ss) = make_float2(su[4*jn+2], su[4*jn+3]);
            int2 mk = *(const int2*)(mbuf + colL * 4);
            float s0 = mk.x ? sv[4*jn]   : NEGINF;
            float s1 = mk.y ? sv[4*jn+1] : NEGINF;
            float s2 = mk.x ? sv[4*jn+2] : NEGINF;
            float s3 = mk.y ? sv[4*jn+3] : NEGINF;
            float g0 = __fdividef(1.f, 1.f + __expf(-su[4*jn]))   + 1e-6f;
            float g1 = __fdividef(1.f, 1.f + __expf(-su[4*jn+1])) + 1e-6f;
            float g2 = __fdividef(1.f, 1.f + __expf(-su[4*jn+2])) + 1e-6f;
            float g3 = __fdividef(1.f, 1.f + __expf(-su[4*jn+3])) + 1e-6f;
            float p0 = __expf(s0) * g0;
            float p1 = __expf(s1) * g1;
            float p2 = __expf(s2) * g2;
            float p3 = __expf(s3) * g3;
            lsum0 += p0 + p1;
            lsum1 += p2 + p3;
            int t = jn >> 1, o = (jn & 1) * 2;
            pa[t][o]     = packh2(p0, p1);
            pa[t][o + 1] = packh2(p2, p3);
        }

#pragma unroll
        for (int t = 0; t < 2; t++) {
#pragma unroll
            for (int g = 0; g < 4; g++) {
                uint32_t vro = (uint32_t)((t * 16 + (lid & 15)) * 128)
                             + (uint32_t)(((2 * g + ((lid >> 4) & 1)) ^ (lid & 7)) << 4);
                uint32_t vh[4];
                LDSM_X4_T(vh[0], vh[1], vh[2], vh[3], cbuf + 12288 + vro);
                MMAF16(out + 4*(2*g),   pa[t], vh[0], vh[1]);
                MMAF16(out + 4*(2*g+1), pa[t], vh[2], vh[3]);
            }
        }
        __syncthreads();
    }

    lsum0 += __shfl_xor_sync(0xffffffffu, lsum0, 1);
    lsum0 += __shfl_xor_sync(0xffffffffu, lsum0, 2);
    lsum1 += __shfl_xor_sync(0xffffffffu, lsum1, 1);
    lsum1 += __shfl_xor_sync(0xffffffffu, lsum1, 2);
    float i0 = 1.f / lsum0, i1 = 1.f / lsum1;
    size_t r0g = (size_t)(b * Ss + row0);
#pragma unroll
    for (int dn = 0; dn < 8; dn++) {
        int col = h * 64 + dn * 8 + mcol;
        *(uint32_t*)(of + r0g * Hh + col)       = packh2(out[4*dn] * i0,   out[4*dn+1] * i0);
        *(uint32_t*)(of + (r0g + 8) * Hh + col) = packh2(out[4*dn+2] * i1, out[4*dn+3] * i1);
    }
}

// ---------------- launch ----------------
extern "C" void kernel_launch(void* const* d_in, const int* in_sizes, int n_in,
                              void* d_out, int out_size)
{
    (void)in_sizes; (void)n_in; (void)out_size;
    const float* x    = (const float*)d_in[0];
    const int*   mask = (const int*)  d_in[1];
    const float* Wq   = (const float*)d_in[2];
    const float* bq   = (const float*)d_in[3];
    const float* Wk   = (const float*)d_in[4];
    const float* bk   = (const float*)d_in[5];
    const float* Wv   = (const float*)d_in[6];
    const float* bv   = (const float*)d_in[7];
    const float* Wo   = (const float*)d_in[8];
    const float* bo   = (const float*)d_in[9];
    const float* Wti  = (const float*)d_in[10];
    const float* bti  = (const float*)d_in[11];
    const float* temb = (const float*)d_in[12];
    const float* Wqt  = (const float*)d_in[13];
    const float* bqt  = (const float*)d_in[14];
    const float* Wkt  = (const float*)d_in[15];
    const float* bkt  = (const float*)d_in[16];
    const float* Wbil = (const float*)d_in[17];

    float* out      = (float*)d_out;
    float* out_y    = out;
    float* out_tl   = out + (size_t)TOKS * Hh;
    float* out_unif = out_tl + (size_t)TOKS * NTt;

    float* qt;
    __nv_bfloat16 *kth, *ktl, *qwh, *qwl;
    __half *xf, *wf, *qfp, *kfp, *vfp;
    cudaGetSymbolAddress((void**)&qt,   g_qt);
    cudaGetSymbolAddress((void**)&xf,   g_xf);
    cudaGetSymbolAddress((void**)&wf,   g_wf);
    cudaGetSymbolAddress((void**)&qfp,  g_qf);
    cudaGetSymbolAddress((void**)&kfp,  g_kf);
    cudaGetSymbolAddress((void**)&vfp,  g_vf);
    cudaGetSymbolAddress((void**)&kth,  g_kthi);
    cudaGetSymbolAddress((void**)&ktl,  g_ktlo);
    cudaGetSymbolAddress((void**)&qwh,  g_qwhi);
    cudaGetSymbolAddress((void**)&qwl,  g_qwlo);

    const size_t WSZ = (size_t)Hh * Hh;
    cvt_f16<<<(TOKS * Hh / 4 + 1023) / 1024, 256>>>((const float4*)x, xf, TOKS * Hh / 4);
    cvt_f16_w4<<<dim3((WSZ / 4 + 1023) / 1024, 4), 256>>>(
        (const float4*)Wq, (const float4*)Wk, (const float4*)Wv, (const float4*)Wo, wf);

    cudaFuncSetAttribute(gemm_qkv_f16, cudaFuncAttributeMaxDynamicSharedMemorySize, GF_SMEM);
    cudaFuncSetAttribute(gemm_o_f16,   cudaFuncAttributeMaxDynamicSharedMemorySize, GF_SMEM);
    gemm_qkv_f16<<<dim3(GN / 128, TOKS / 128, 3), 256, GF_SMEM>>>(
        xf, wf, bq, bk, bv, qfp, kfp, vfp);

    cudaFuncSetAttribute(type_kernel3, cudaFuncAttributeMaxDynamicSharedMemorySize, TK_SMEM);
    type_kernel3<<<TOKS / 16, 512, TK_SMEM>>>(x, Wti, bti, temb, Wqt, bqt, Wkt, bkt,
                                              out_tl, qt, kth, ktl);

    qtw_kernel<<<dim3(TOKS / 64, NHh), 256>>>(qt, Wbil, qwh, qwl);

    cudaFuncSetAttribute(attn_hmma, cudaFuncAttributeMaxDynamicSharedMemorySize, ATT_SMEM);
    // attn output (fp16) reuses g_xf: x is no longer needed after gemm_qkv/type_kernel
    attn_hmma<<<dim3(Ss / 64, NHh, Bb), 128, ATT_SMEM>>>(qfp, kfp, vfp,
        kth, ktl, qwh, qwl, mask, out_unif, xf);

    gemm_o_f16<<<dim3(GN / 128, TOKS / 128), 256, GF_SMEM>>>(xf, wf, bo, out_y);
}

// round 16
// speedup vs baseline: 1.1148x; 1.0082x over previous
#include <cuda_runtime.h>
#include <cuda_bf16.h>
#include <cuda_fp16.h>
#include <cstdint>
#include <cstddef>

#define Bb 2
#define Ss 2048
#define Hh 1024
#define NHh 16
#define HDd 64
#define NTt 5
#define TOKS (Bb*Ss)          /* 4096 */
#define SCALE 0.125f          /* 1/sqrt(64) */
#define L2E 1.44269504f

// ---------------- scratch (static device globals; no allocation) ----------------
__device__ float g_qt[(size_t)TOKS*HDd];
__device__ __half g_xf[(size_t)TOKS*Hh];         /* x fp16, later reused as attn-out fp16 */
__device__ __half g_wf[(size_t)4*Hh*Hh];         /* Wq,Wk,Wv,Wo fp16 */
__device__ __half g_qf[(size_t)TOKS*Hh];
__device__ __half g_kf[(size_t)TOKS*Hh];
__device__ __half g_vf[(size_t)TOKS*Hh];
__device__ __nv_bfloat16 g_kthi[(size_t)TOKS*HDd];
__device__ __nv_bfloat16 g_ktlo[(size_t)TOKS*HDd];
__device__ __nv_bfloat16 g_qwhi[(size_t)Bb*NHh*Ss*HDd];
__device__ __nv_bfloat16 g_qwlo[(size_t)Bb*NHh*Ss*HDd];

// ================= low-level helpers (all plain sm_75+/sm_80+ features) =================
__device__ __forceinline__ uint32_t smem_u32(const void* p) {
    uint32_t a;
    asm("{ .reg .u64 t; cvta.to.shared.u64 t, %1; cvt.u32.u64 %0, t; }" : "=r"(a) : "l"(p));
    return a;
}
#define CP_ASYNC16(saddr, gaddr) \
    asm volatile("cp.async.cg.shared.global [%0], [%1], 16;" :: "r"(saddr), "l"(gaddr))
#define CP_COMMIT() asm volatile("cp.async.commit_group;" ::: "memory")
#define CP_WAIT1()  asm volatile("cp.async.wait_group 1;" ::: "memory")
#define CP_WAIT0()  asm volatile("cp.async.wait_group 0;" ::: "memory")
#define LDSM_X4(r0, r1, r2, r3, addr) \
    asm volatile("ldmatrix.sync.aligned.m8n8.x4.shared.b16 {%0,%1,%2,%3}, [%4];" \
        : "=r"(r0), "=r"(r1), "=r"(r2), "=r"(r3) : "r"(addr))
#define LDSM_X4_T(r0, r1, r2, r3, addr) \
    asm volatile("ldmatrix.sync.aligned.m8n8.x4.trans.shared.b16 {%0,%1,%2,%3}, [%4];" \
        : "=r"(r0), "=r"(r1), "=r"(r2), "=r"(r3) : "r"(addr))
#define MMA16816(c, a, b0, b1) \
    asm volatile("mma.sync.aligned.m16n8k16.row.col.f32.bf16.bf16.f32 " \
        "{%0,%1,%2,%3}, {%4,%5,%6,%7}, {%8,%9}, {%0,%1,%2,%3};" \
        : "+f"((c)[0]), "+f"((c)[1]), "+f"((c)[2]), "+f"((c)[3]) \
        : "r"((a)[0]), "r"((a)[1]), "r"((a)[2]), "r"((a)[3]), "r"(b0), "r"(b1))
#define MMAF16(c, a, b0, b1) \
    asm volatile("mma.sync.aligned.m16n8k16.row.col.f32.f16.f16.f32 " \
        "{%0,%1,%2,%3}, {%4,%5,%6,%7}, {%8,%9}, {%0,%1,%2,%3};" \
        : "+f"((c)[0]), "+f"((c)[1]), "+f"((c)[2]), "+f"((c)[3]) \
        : "r"((a)[0]), "r"((a)[1]), "r"((a)[2]), "r"((a)[3]), "r"(b0), "r"(b1))
#define EX2_F16X2(d, a)  asm volatile("ex2.approx.f16x2 %0, %1;"  : "=r"(d) : "r"(a))
#define TANH_F16X2(d, a) asm volatile("tanh.approx.f16x2 %0, %1;" : "=r"(d) : "r"(a))

__device__ __forceinline__ void split2(float x, float y, uint32_t& hi, uint32_t& lo) {
    __nv_bfloat16 hx = __float2bfloat16(x), hy = __float2bfloat16(y);
    __nv_bfloat16 lx = __float2bfloat16(x - __bfloat162float(hx));
    __nv_bfloat16 ly = __float2bfloat16(y - __bfloat162float(hy));
    __nv_bfloat162 h2(hx, hy), l2(lx, ly);
    hi = *(uint32_t*)&h2; lo = *(uint32_t*)&l2;
}
__device__ __forceinline__ uint32_t packh2(float x, float y) {
    __half2 h = __floats2half2_rn(x, y);
    return *(uint32_t*)&h;
}

// ================= conversions =================
__global__ __launch_bounds__(256)
void cvt_f16(const float4* __restrict__ in, __half* __restrict__ out, int n4)
{
    int base = blockIdx.x * 1024 + threadIdx.x;
    float4 f[4];
    int idx[4];
#pragma unroll
    for (int u = 0; u < 4; u++) {
        idx[u] = base + u * 256;
        if (idx[u] < n4) f[u] = in[idx[u]];
    }
#pragma unroll
    for (int u = 0; u < 4; u++) {
        if (idx[u] >= n4) continue;
        uint2 o;
        o.x = packh2(f[u].x, f[u].y);
        o.y = packh2(f[u].z, f[u].w);
        *(uint2*)(out + (size_t)idx[u] * 4) = o;
    }
}

__global__ __launch_bounds__(256)
void cvt_f16_w4(const float4* __restrict__ W0, const float4* __restrict__ W1,
                const float4* __restrict__ W2, const float4* __restrict__ W3,
                __half* __restrict__ out)
{
    const int n4 = Hh * Hh / 4;
    int z = blockIdx.y;
    const float4* in = (z == 0) ? W0 : (z == 1) ? W1 : (z == 2) ? W2 : W3;
    int base = blockIdx.x * 1024 + threadIdx.x;
    float4 f[4];
    int idx[4];
#pragma unroll
    for (int u = 0; u < 4; u++) {
        idx[u] = base + u * 256;
        if (idx[u] < n4) f[u] = in[idx[u]];
    }
    size_t zb = (size_t)z * Hh * Hh;
#pragma unroll
    for (int u = 0; u < 4; u++) {
        if (idx[u] >= n4) continue;
        uint2 o;
        o.x = packh2(f[u].x, f[u].y);
        o.y = packh2(f[u].z, f[u].w);
        *(uint2*)(out + zb + (size_t)idx[u] * 4) = o;
    }
}

// ================= fp16 single-term GEMM body: C = A @ W^T + b =================
#define GN 1024
#define GF_BUF 32768
#define GF_SMEM (2*GF_BUF + 512)

__device__ __forceinline__ void gemm_f16_body(
    const __half* __restrict__ Af, const __half* __restrict__ Wf,
    const float* __restrict__ bias, float oscale,
    __half* __restrict__ Ch, float* __restrict__ Cf,
    char* sm_, int bm, int bn)
{
    uint32_t sb = smem_u32(sm_);
    float* bias_s = (float*)(sm_ + 2 * GF_BUF);
    int tid = threadIdx.x, wid = tid >> 5, lid = tid & 31;
    if (tid < 128) bias_s[tid] = bias[bn + tid];

    int warp_row = (wid & 1) * 64;
    int warp_col = (wid >> 1) * 32;
    int sub = lid & 7;
    int gA1 = (lid >> 3) & 1, ca = (lid >> 4) & 1;
    int gB2 = (lid >> 4) & 1, cb = (lid >> 3) & 1;

    uint32_t aBase[4], bBase[2];
#pragma unroll
    for (int i = 0; i < 4; i++)
        aBase[i] = (uint32_t)((warp_row + i * 16 + gA1 * 8 + sub) * 128);
#pragma unroll
    for (int p = 0; p < 2; p++)
        bBase[p] = (uint32_t)((warp_col + p * 16 + gB2 * 8 + sub) * 128);

    float acc[4][4][4];
#pragma unroll
    for (int i = 0; i < 4; i++)
#pragma unroll
        for (int jn = 0; jn < 4; jn++)
#pragma unroll
            for (int r = 0; r < 4; r++) acc[i][jn][r] = 0.f;

#pragma unroll
    for (int i = tid; i < 1024; i += 256) {
        int r = i >> 3, c = i & 7;
        uint32_t sw = (uint32_t)(r * 128) + (uint32_t)((c ^ (r & 7)) << 4);
        CP_ASYNC16(sb + sw,           (const char*)Af + (((size_t)(bm + r)) << 11) + (c << 4));
        CP_ASYNC16(sb + 16384 + sw,   (const char*)Wf + (((size_t)(bn + r)) << 11) + (c << 4));
    }
    CP_COMMIT();

    for (int c = 0; c < 16; c++) {
        if (c + 1 < 16) {
            uint32_t nbuf = sb + ((c + 1) & 1) * GF_BUF;
            int kcb = (c + 1) * 128;
#pragma unroll
            for (int i = tid; i < 1024; i += 256) {
                int r = i >> 3, cc = i & 7;
                uint32_t sw = (uint32_t)(r * 128) + (uint32_t)((cc ^ (r & 7)) << 4);
                CP_ASYNC16(nbuf + sw,         (const char*)Af + (((size_t)(bm + r)) << 11) + kcb + (cc << 4));
                CP_ASYNC16(nbuf + 16384 + sw, (const char*)Wf + (((size_t)(bn + r)) << 11) + kcb + (cc << 4));
            }
            CP_COMMIT();
            CP_WAIT1();
        } else {
            CP_WAIT0();
        }
        __syncthreads();

        uint32_t bufoff = sb + (c & 1) * GF_BUF;
#pragma unroll
        for (int j = 0; j < 4; j++) {
            uint32_t ah[4][4], bh[2][4];
#pragma unroll
            for (int i = 0; i < 4; i++) {
                uint32_t ad = bufoff + aBase[i] + (uint32_t)(((2 * j + ca) ^ sub) << 4);
                LDSM_X4(ah[i][0], ah[i][1], ah[i][2], ah[i][3], ad);
            }
#pragma unroll
            for (int p = 0; p < 2; p++) {
                uint32_t bd = bufoff + 16384 + bBase[p] + (uint32_t)(((2 * j + cb) ^ sub) << 4);
                LDSM_X4(bh[p][0], bh[p][1], bh[p][2], bh[p][3], bd);
            }
#pragma unroll
            for (int i = 0; i < 4; i++) {
#pragma unroll
                for (int jn = 0; jn < 4; jn++) {
                    int p = jn >> 1, q = (jn & 1) * 2;
                    MMAF16(acc[i][jn], ah[i], bh[p][q], bh[p][q + 1]);
                }
            }
        }
        __syncthreads();
    }

    int lr = lid >> 2, lc = (lid & 3) * 2;
#pragma unroll
    for (int i = 0; i < 4; i++) {
#pragma unroll
        for (int jn = 0; jn < 4; jn++) {
            int row = bm + warp_row + i * 16 + lr;
            int colL = warp_col + jn * 8 + lc;
            int col = bn + colL;
            float b0 = bias_s[colL], b1 = bias_s[colL + 1];
            float v00 = (acc[i][jn][0] + b0) * oscale, v01 = (acc[i][jn][1] + b1) * oscale;
            float v10 = (acc[i][jn][2] + b0) * oscale, v11 = (acc[i][jn][3] + b1) * oscale;
            if (Ch) {
                *(uint32_t*)(Ch + (size_t)row * GN + col)       = packh2(v00, v01);
                *(uint32_t*)(Ch + (size_t)(row + 8) * GN + col) = packh2(v10, v11);
            } else {
                *(float2*)(Cf + (size_t)row * GN + col)       = make_float2(v00, v01);
                *(float2*)(Cf + (size_t)(row + 8) * GN + col) = make_float2(v10, v11);
            }
        }
    }
}

// fused Q/K/V projection: grid.z selects. Q pre-scaled by 1/8 (exact).
__global__ __launch_bounds__(256)
void gemm_qkv_f16(const __half* __restrict__ xf, const __half* __restrict__ wf,
                  const float* __restrict__ bq, const float* __restrict__ bk,
                  const float* __restrict__ bv,
                  __half* __restrict__ qf, __half* __restrict__ kf, __half* __restrict__ vf)
{
    extern __shared__ char sm_[];
    int z = blockIdx.z;
    const __half* Wf = wf + (size_t)z * Hh * Hh;
    const float* bias = (z == 0) ? bq : (z == 1) ? bk : bv;
    __half* Ch = (z == 0) ? qf : (z == 1) ? kf : vf;
    float oscale = (z == 0) ? SCALE : 1.f;
    gemm_f16_body(xf, Wf, bias, oscale, Ch, nullptr, sm_,
                  blockIdx.y * 128, blockIdx.x * 128);
}

// O projection: fp16 inputs, fp32 output
__global__ __launch_bounds__(256)
void gemm_o_f16(const __half* __restrict__ of, const __half* __restrict__ wf,
                const float* __restrict__ bias, float* __restrict__ Cf)
{
    extern __shared__ char sm_[];
    gemm_f16_body(of, wf + (size_t)3 * Hh * Hh, bias, 1.f, nullptr, Cf, sm_,
                  blockIdx.y * 128, blockIdx.x * 128);
}

// ---------------- type inference v3: warp-per-token, all weights in smem ----------------
#define TK_SMEM ((NTt*Hh + NTt*HDd + 16*HDd + 2*HDd*65) * 4)

__global__ __launch_bounds__(512)
void type_kernel3(const float* __restrict__ x, const float* __restrict__ Wti,
                  const float* __restrict__ bti, const float* __restrict__ temb,
                  const float* __restrict__ Wqt, const float* __restrict__ bqt,
                  const float* __restrict__ Wkt, const float* __restrict__ bkt,
                  float* __restrict__ tl_out, float* __restrict__ qt,
                  __nv_bfloat16* __restrict__ kthi, __nv_bfloat16* __restrict__ ktlo)
{
    extern __shared__ float smf[];
    float* sWti  = smf;
    float* stemb = sWti + NTt * Hh;
    float* slat  = stemb + NTt * HDd;
    float* sWqt  = slat + 16 * HDd;
    float* sWkt  = sWqt + HDd * 65;

    int tid = threadIdx.x, wid = tid >> 5, lid = tid & 31;
    for (int i = tid; i < NTt * Hh; i += 512) sWti[i] = Wti[i];
    for (int i = tid; i < NTt * HDd; i += 512) stemb[i] = temb[i];
    for (int i = tid; i < HDd * HDd; i += 512) {
        int r = i >> 6, c = i & 63;
        sWqt[r * 65 + c] = Wqt[i];
        sWkt[r * 65 + c] = Wkt[i];
    }
    __syncthreads();

    int tok = blockIdx.x * 16 + wid;
    const float* xr = x + (size_t)tok * Hh;
    float xv[32];
#pragma unroll
    for (int j = 0; j < 32; j++) xv[j] = xr[lid + 32 * j];

    float lg[NTt];
#pragma unroll
    for (int t = 0; t < NTt; t++) {
        float s = 0.f;
#pragma unroll
        for (int j = 0; j < 32; j++) s += xv[j] * sWti[t * Hh + lid + 32 * j];
        s += __shfl_xor_sync(0xffffffffu, s, 16);
        s += __shfl_xor_sync(0xffffffffu, s, 8);
        s += __shfl_xor_sync(0xffffffffu, s, 4);
        s += __shfl_xor_sync(0xffffffffu, s, 2);
        s += __shfl_xor_sync(0xffffffffu, s, 1);
        lg[t] = s + bti[t];
    }
    if (lid == 0) {
        float* tl = tl_out + (size_t)tok * NTt;
#pragma unroll
        for (int t = 0; t < NTt; t++) tl[t] = lg[t];
    }
    float mx = lg[0];
#pragma unroll
    for (int t = 1; t < NTt; t++) mx = fmaxf(mx, lg[t]);
    float e[NTt], se = 0.f;
#pragma unroll
    for (int t = 0; t < NTt; t++) { e[t] = expf(lg[t] - mx); se += e[t]; }
    float inv = 1.f / se;

    float la0 = 0.f, la1 = 0.f;
#pragma unroll
    for (int t = 0; t < NTt; t++) {
        float p = e[t] * inv;
        la0 += p * stemb[t * HDd + lid];
        la1 += p * stemb[t * HDd + lid + 32];
    }
    slat[wid * HDd + lid] = la0;
    slat[wid * HDd + lid + 32] = la1;
    __syncwarp();

#pragma unroll
    for (int rep = 0; rep < 2; rep++) {
        int d = lid + rep * 32;
        float a = bqt[d], c = bkt[d];
        const float* wq = sWqt + d * 65;
        const float* wk = sWkt + d * 65;
        const float* la = slat + wid * HDd;
#pragma unroll
        for (int e2 = 0; e2 < HDd; e2++) {
            float lv = la[e2];
            a += lv * wq[e2];
            c += lv * wk[e2];
        }
        qt[(size_t)tok * HDd + d] = a;
        __nv_bfloat16 hc = __float2bfloat16(c);
        kthi[(size_t)tok * HDd + d] = hc;
        ktlo[(size_t)tok * HDd + d] = __float2bfloat16(c - __bfloat162float(hc));
    }
}

// ---------------- qtW (pre-scaled by 1/8, exact) ----------------
__global__ __launch_bounds__(256)
void qtw_kernel(const float* __restrict__ qt, const float* __restrict__ Wb,
                __nv_bfloat16* __restrict__ qwhi, __nv_bfloat16* __restrict__ qwlo)
{
    __shared__ float Qs[64][65];
    __shared__ float Ws[64][65];
    int h = blockIdx.y;
    int t0 = blockIdx.x * 64;
    int tid = threadIdx.x;
    for (int i = tid; i < 4096; i += 256) {
        int r = i >> 6, c = i & 63;
        Qs[r][c] = qt[(size_t)(t0 + r) * HDd + c];
        Ws[r][c] = Wb[(size_t)h * 4096 + i];
    }
    __syncthreads();
    int tx = tid & 15, ty = tid >> 4;
    float acc[4][4];
#pragma unroll
    for (int i = 0; i < 4; i++)
#pragma unroll
        for (int j = 0; j < 4; j++) acc[i][j] = 0.f;
#pragma unroll 4
    for (int d = 0; d < 64; d++) {
        float a[4], b[4];
#pragma unroll
        for (int i = 0; i < 4; i++) a[i] = Qs[ty * 4 + i][d];
#pragma unroll
        for (int j = 0; j < 4; j++) b[j] = Ws[d][tx * 4 + j];
#pragma unroll
        for (int i = 0; i < 4; i++)
#pragma unroll
            for (int j = 0; j < 4; j++) acc[i][j] += a[i] * b[j];
    }
#pragma unroll
    for (int i = 0; i < 4; i++) {
        int tok = t0 + ty * 4 + i;
        int b = tok >> 11;
        int qq = tok & 2047;
        size_t base = (((size_t)(b * NHh + h)) * Ss + qq) * HDd + tx * 4;
        uint32_t h0, l0, h1, l1;
        split2(acc[i][0] * SCALE, acc[i][1] * SCALE, h0, l0);
        split2(acc[i][2] * SCALE, acc[i][3] * SCALE, h1, l1);
        uint2 hv = make_uint2(h0, h1), lv = make_uint2(l0, l1);
        *(uint2*)(qwhi + base) = hv;
        *(uint2*)(qwlo + base) = lv;
    }
}

// ================= HMMA flash attention v6: f16x2 transcendentals =================
#define AKV 16512
#define ATT_QREG 24576
#define ATT_SMEM (ATT_QREG + 2*AKV)   /* 57600 */
#define NKT (Ss/32)

__device__ __forceinline__ void att_load_kv(uint32_t dst, int b, int h, int k0, int tid,
    const __half* kf, const __nv_bfloat16* kthi, const __nv_bfloat16* ktlo,
    const __half* vf, const int* mask)
{
#pragma unroll
    for (int i = tid; i < 256; i += 128) {
        int r = i >> 3, c = i & 7;
        uint32_t sw = (uint32_t)(r * 128) + (uint32_t)((c ^ (r & 7)) << 4);
        size_t gk = ((size_t)(b * Ss + k0 + r)) * 2048 + h * 128 + (c << 4);
        size_t gt = ((size_t)(b * Ss + k0 + r)) * 128 + (c << 4);
        CP_ASYNC16(dst + sw,          (const char*)kf + gk);
        CP_ASYNC16(dst + 4096 + sw,   (const char*)kthi + gt);
        CP_ASYNC16(dst + 8192 + sw,   (const char*)ktlo + gt);
        CP_ASYNC16(dst + 12288 + sw,  (const char*)vf + gk);
    }
    if (tid < 8)
        CP_ASYNC16(dst + 16384 + tid * 16, (const char*)mask + ((size_t)(b * Ss + k0)) * 4 + tid * 16);
}

__global__ __launch_bounds__(128, 3)
void attn_hmma(const __half* __restrict__ qf, const __half* __restrict__ kf,
               const __half* __restrict__ vf,
               const __nv_bfloat16* __restrict__ kthi, const __nv_bfloat16* __restrict__ ktlo,
               const __nv_bfloat16* __restrict__ qwhi, const __nv_bfloat16* __restrict__ qwlo,
               const int* __restrict__ mask, float* __restrict__ unif,
               __half* __restrict__ of)
{
    extern __shared__ char sm_[];
    uint32_t sb = smem_u32(sm_);
    int tid = threadIdx.x, wid = tid >> 5, lid = tid & 31;
    int b = blockIdx.z, h = blockIdx.y, q0 = blockIdx.x * 64;
    const float NEGINF = __int_as_float(0xff800000);
    const __half2 H05 = __float2half2_rn(0.5f);

#pragma unroll
    for (int i = tid; i < 512; i += 128) {
        int r = i >> 3, c = i & 7;
        uint32_t sw = (uint32_t)(r * 128) + (uint32_t)((c ^ (r & 7)) << 4);
        size_t gq = ((size_t)(b * Ss + q0 + r)) * 2048 + h * 128 + (c << 4);
        size_t gw = (((size_t)(b * NHh + h)) * Ss + q0 + r) * 128 + (c << 4);
        CP_ASYNC16(sb + sw,          (const char*)qf + gq);
        CP_ASYNC16(sb + 8192 + sw,   (const char*)qwhi + gw);
        CP_ASYNC16(sb + 16384 + sw,  (const char*)qwlo + gw);
    }
    att_load_kv(sb + ATT_QREG, b, h, 0, tid, kf, kthi, ktlo, vf, mask);
    CP_COMMIT();

    int sub = lid & 7;
    int gA1 = (lid >> 3) & 1, ca = (lid >> 4) & 1;
    int gB2 = (lid >> 4) & 1, cb = (lid >> 3) & 1;
    int arow = wid * 16 + gA1 * 8 + sub;
    uint32_t aoffQ[4];
#pragma unroll
    for (int j = 0; j < 4; j++)
        aoffQ[j] = (uint32_t)(arow * 128) + (uint32_t)(((2 * j + ca) ^ sub) << 4);

    uint32_t qfr[4][4];
    float out[32], sv[16], su[16];
    float lsum0 = 0.f, lsum1 = 0.f;
#pragma unroll
    for (int i = 0; i < 32; i++) out[i] = 0.f;

    int row0 = q0 + wid * 16 + (lid >> 2);
    int mcol = 2 * (lid & 3);

    for (int kt = 0; kt < NKT; kt++) {
        if (kt + 1 < NKT) {
            att_load_kv(sb + ATT_QREG + ((kt + 1) & 1) * AKV, b, h, (kt + 1) * 32, tid,
                        kf, kthi, ktlo, vf, mask);
            CP_COMMIT();
            CP_WAIT1();
        } else {
            CP_WAIT0();
        }
        __syncthreads();

        if (kt == 0) {
#pragma unroll
            for (int j = 0; j < 4; j++)
                LDSM_X4(qfr[j][0], qfr[j][1], qfr[j][2], qfr[j][3], sb + aoffQ[j]);
        }

        uint32_t cbuf = sb + ATT_QREG + (kt & 1) * AKV;
        int k0 = kt * 32;
#pragma unroll
        for (int i = 0; i < 16; i++) { sv[i] = 0.f; su[i] = 0.f; }

        // ---- val scores: Q . K^T  (fp16 single-term, Q pre-scaled by 1/8) ----
#pragma unroll
        for (int j = 0; j < 4; j++) {
            uint32_t bh[8];
#pragma unroll
            for (int p = 0; p < 2; p++) {
                uint32_t bo = (uint32_t)((p * 16 + gB2 * 8 + sub) * 128)
                            + (uint32_t)(((2 * j + cb) ^ sub) << 4);
                LDSM_X4(bh[4*p], bh[4*p+1], bh[4*p+2], bh[4*p+3], cbuf + bo);
            }
#pragma unroll
            for (int jn = 0; jn < 4; jn++) {
                int bi = (jn >> 1) * 4 + (jn & 1) * 2;
                MMAF16(sv + 4*jn, qfr[j], bh[bi], bh[bi+1]);
            }
        }
        // ---- unif scores: QW . KT^T  (bf16 3-term) ----
#pragma unroll
        for (int j = 0; j < 4; j++) {
            uint32_t aw_h[4], aw_l[4], bh[8], bl[8];
            LDSM_X4(aw_h[0], aw_h[1], aw_h[2], aw_h[3], sb + 8192 + aoffQ[j]);
            LDSM_X4(aw_l[0], aw_l[1], aw_l[2], aw_l[3], sb + 16384 + aoffQ[j]);
#pragma unroll
            for (int p = 0; p < 2; p++) {
                uint32_t bo = (uint32_t)((p * 16 + gB2 * 8 + sub) * 128)
                            + (uint32_t)(((2 * j + cb) ^ sub) << 4);
                LDSM_X4(bh[4*p], bh[4*p+1], bh[4*p+2], bh[4*p+3], cbuf + 4096 + bo);
                LDSM_X4(bl[4*p], bl[4*p+1], bl[4*p+2], bl[4*p+3], cbuf + 8192 + bo);
            }
#pragma unroll
            for (int jn = 0; jn < 4; jn++) {
                int bi = (jn >> 1) * 4 + (jn & 1) * 2;
                MMA16816(su + 4*jn, aw_h, bh[bi], bh[bi+1]);
                MMA16816(su + 4*jn, aw_h, bl[bi], bl[bi+1]);
                MMA16816(su + 4*jn, aw_l, bh[bi], bh[bi+1]);
            }
        }

        // ---- elementwise: unif store, mask, p = exp(s)*sigmoid(u) via f16x2 MUFU ----
        const char* mbuf = sm_ + ATT_QREG + (kt & 1) * AKV + 16384;
        uint32_t pa[2][4];
        __half2 acc01 = __float2half2_rn(0.f), acc23 = __float2half2_rn(0.f);
#pragma unroll
        for (int jn = 0; jn < 4; jn++) {
            int colL = jn * 8 + mcol;
            size_t ub = (((size_t)(b * NHh + h)) * Ss + row0) * Ss + k0 + colL;
            *(float2*)(unif + ub)          = make_float2(su[4*jn],   su[4*jn+1]);
            *(float2*)(unif + ub + 8 * Ss) = make_float2(su[4*jn+2], su[4*jn+3]);
            int2 mk = *(const int2*)(mbuf + colL * 4);
            float s0 = mk.x ? sv[4*jn]   * L2E : NEGINF;
            float s1 = mk.y ? sv[4*jn+1] * L2E : NEGINF;
            float s2 = mk.x ? sv[4*jn+2] * L2E : NEGINF;
            float s3 = mk.y ? sv[4*jn+3] * L2E : NEGINF;
            uint32_t es01 = packh2(s0, s1), es23 = packh2(s2, s3);
            uint32_t hu01 = packh2(su[4*jn]   * 0.5f, su[4*jn+1] * 0.5f);
            uint32_t hu23 = packh2(su[4*jn+2] * 0.5f, su[4*jn+3] * 0.5f);
            uint32_t e01, e23, t01, t23;
            EX2_F16X2(e01, es01);
            EX2_F16X2(e23, es23);
            TANH_F16X2(t01, hu01);
            TANH_F16X2(t23, hu23);
            __half2 sig01 = __hfma2(*(__half2*)&t01, H05, H05);
            __half2 sig23 = __hfma2(*(__half2*)&t23, H05, H05);
            __half2 p01 = __hmul2(*(__half2*)&e01, sig01);
            __half2 p23 = __hmul2(*(__half2*)&e23, sig23);
            acc01 = __hadd2(acc01, p01);
            acc23 = __hadd2(acc23, p23);
            int t = jn >> 1, o = (jn & 1) * 2;
            pa[t][o]     = *(uint32_t*)&p01;
            pa[t][o + 1] = *(uint32_t*)&p23;
        }
        {
            float2 a01 = __half22float2(acc01);
            float2 a23 = __half22float2(acc23);
            lsum0 += a01.x + a01.y;
            lsum1 += a23.x + a23.y;
        }

        // ---- PV: out += P . V  (fp16 single-term) ----
#pragma unroll
        for (int t = 0; t < 2; t++) {
#pragma unroll
            for (int g = 0; g < 4; g++) {
                uint32_t vro = (uint32_t)((t * 16 + (lid & 15)) * 128)
                             + (uint32_t)(((2 * g + ((lid >> 4) & 1)) ^ (lid & 7)) << 4);
                uint32_t vh[4];
                LDSM_X4_T(vh[0], vh[1], vh[2], vh[3], cbuf + 12288 + vro);
                MMAF16(out + 4*(2*g),   pa[t], vh[0], vh[1]);
                MMAF16(out + 4*(2*g+1), pa[t], vh[2], vh[3]);
            }
        }
        __syncthreads();
    }

    lsum0 += __shfl_xor_sync(0xffffffffu, lsum0, 1);
    lsum0 += __shfl_xor_sync(0xffffffffu, lsum0, 2);
    lsum1 += __shfl_xor_sync(0xffffffffu, lsum1, 1);
    lsum1 += __shfl_xor_sync(0xffffffffu, lsum1, 2);
    float i0 = 1.f / lsum0, i1 = 1.f / lsum1;
    size_t r0g = (size_t)(b * Ss + row0);
#pragma unroll
    for (int dn = 0; dn < 8; dn++) {
        int col = h * 64 + dn * 8 + mcol;
        *(uint32_t*)(of + r0g * Hh + col)       = packh2(out[4*dn] * i0,   out[4*dn+1] * i0);
        *(uint32_t*)(of + (r0g + 8) * Hh + col) = packh2(out[4*dn+2] * i1, out[4*dn+3] * i1);
    }
}

// ---------------- launch ----------------
extern "C" void kernel_launch(void* const* d_in, const int* in_sizes, int n_in,
                              void* d_out, int out_size)
{
    (void)in_sizes; (void)n_in; (void)out_size;
    const float* x    = (const float*)d_in[0];
    const int*   mask = (const int*)  d_in[1];
    const float* Wq   = (const float*)d_in[2];
    const float* bq   = (const float*)d_in[3];
    const float* Wk   = (const float*)d_in[4];
    const float* bk   = (const float*)d_in[5];
    const float* Wv   = (const float*)d_in[6];
    const float* bv   = (const float*)d_in[7];
    const float* Wo   = (const float*)d_in[8];
    const float* bo   = (const float*)d_in[9];
    const float* Wti  = (const float*)d_in[10];
    const float* bti  = (const float*)d_in[11];
    const float* temb = (const float*)d_in[12];
    const float* Wqt  = (const float*)d_in[13];
    const float* bqt  = (const float*)d_in[14];
    const float* Wkt  = (const float*)d_in[15];
    const float* bkt  = (const float*)d_in[16];
    const float* Wbil = (const float*)d_in[17];

    float* out      = (float*)d_out;
    float* out_y    = out;
    float* out_tl   = out + (size_t)TOKS * Hh;
    float* out_unif = out_tl + (size_t)TOKS * NTt;

    float* qt;
    __nv_bfloat16 *kth, *ktl, *qwh, *qwl;
    __half *xf, *wf, *qfp, *kfp, *vfp;
    cudaGetSymbolAddress((void**)&qt,   g_qt);
    cudaGetSymbolAddress((void**)&xf,   g_xf);
    cudaGetSymbolAddress((void**)&wf,   g_wf);
    cudaGetSymbolAddress((void**)&qfp,  g_qf);
    cudaGetSymbolAddress((void**)&kfp,  g_kf);
    cudaGetSymbolAddress((void**)&vfp,  g_vf);
    cudaGetSymbolAddress((void**)&kth,  g_kthi);
    cudaGetSymbolAddress((void**)&ktl,  g_ktlo);
    cudaGetSymbolAddress((void**)&qwh,  g_qwhi);
    cudaGetSymbolAddress((void**)&qwl,  g_qwlo);

    const size_t WSZ = (size_t)Hh * Hh;
    cvt_f16<<<(TOKS * Hh / 4 + 1023) / 1024, 256>>>((const float4*)x, xf, TOKS * Hh / 4);
    cvt_f16_w4<<<dim3((WSZ / 4 + 1023) / 1024, 4), 256>>>(
        (const float4*)Wq, (const float4*)Wk, (const float4*)Wv, (const float4*)Wo, wf);

    cudaFuncSetAttribute(gemm_qkv_f16, cudaFuncAttributeMaxDynamicSharedMemorySize, GF_SMEM);
    cudaFuncSetAttribute(gemm_o_f16,   cudaFuncAttributeMaxDynamicSharedMemorySize, GF_SMEM);
    gemm_qkv_f16<<<dim3(GN / 128, TOKS / 128, 3), 256, GF_SMEM>>>(
        xf, wf, bq, bk, bv, qfp, kfp, vfp);

    cudaFuncSetAttribute(type_kernel3, cudaFuncAttributeMaxDynamicSharedMemorySize, TK_SMEM);
    type_kernel3<<<TOKS / 16, 512, TK_SMEM>>>(x, Wti, bti, temb, Wqt, bqt, Wkt, bkt,
                                              out_tl, qt, kth, ktl);

    qtw_kernel<<<dim3(TOKS / 64, NHh), 256>>>(qt, Wbil, qwh, qwl);

    cudaFuncSetAttribute(attn_hmma, cudaFuncAttributeMaxDynamicSharedMemorySize, ATT_SMEM);
    attn_hmma<<<dim3(Ss / 64, NHh, Bb), 128, ATT_SMEM>>>(qfp, kfp, vfp,
        kth, ktl, qwh, qwl, mask, out_unif, xf);

    gemm_o_f16<<<dim3(GN / 128, TOKS / 128), 256, GF_SMEM>>>(xf, wf, bo, out_y);
}

// round 17
// speedup vs baseline: 1.1448x; 1.0269x over previous
#include <cuda_runtime.h>
#include <cuda_bf16.h>
#include <cuda_fp16.h>
#include <cstdint>
#include <cstddef>

#define Bb 2
#define Ss 2048
#define Hh 1024
#define NHh 16
#define HDd 64
#define NTt 5
#define TOKS (Bb*Ss)          /* 4096 */
#define SCALE 0.125f          /* 1/sqrt(64) */

// ---------------- scratch (static device globals; no allocation) ----------------
__device__ float g_qt[(size_t)TOKS*HDd];
__device__ __half g_xf[(size_t)TOKS*Hh];         /* x fp16, later reused as attn-out fp16 */
__device__ __half g_wf[(size_t)4*Hh*Hh];         /* Wq,Wk,Wv,Wo fp16 */
__device__ __half g_qf[(size_t)TOKS*Hh];
__device__ __half g_kf[(size_t)TOKS*Hh];
__device__ __half g_vf[(size_t)TOKS*Hh];
__device__ __nv_bfloat16 g_kthi[(size_t)TOKS*HDd];
__device__ __nv_bfloat16 g_ktlo[(size_t)TOKS*HDd];
__device__ __nv_bfloat16 g_qwhi[(size_t)Bb*NHh*Ss*HDd];
__device__ __nv_bfloat16 g_qwlo[(size_t)Bb*NHh*Ss*HDd];

// ================= low-level helpers (all plain sm_80+ features) =================
__device__ __forceinline__ uint32_t smem_u32(const void* p) {
    uint32_t a;
    asm("{ .reg .u64 t; cvta.to.shared.u64 t, %1; cvt.u32.u64 %0, t; }" : "=r"(a) : "l"(p));
    return a;
}
#define CP_ASYNC16(saddr, gaddr) \
    asm volatile("cp.async.cg.shared.global [%0], [%1], 16;" :: "r"(saddr), "l"(gaddr))
#define CP_COMMIT() asm volatile("cp.async.commit_group;" ::: "memory")
#define CP_WAIT1()  asm volatile("cp.async.wait_group 1;" ::: "memory")
#define CP_WAIT0()  asm volatile("cp.async.wait_group 0;" ::: "memory")
#define LDSM_X4(r0, r1, r2, r3, addr) \
    asm volatile("ldmatrix.sync.aligned.m8n8.x4.shared.b16 {%0,%1,%2,%3}, [%4];" \
        : "=r"(r0), "=r"(r1), "=r"(r2), "=r"(r3) : "r"(addr))
#define LDSM_X4_T(r0, r1, r2, r3, addr) \
    asm volatile("ldmatrix.sync.aligned.m8n8.x4.trans.shared.b16 {%0,%1,%2,%3}, [%4];" \
        : "=r"(r0), "=r"(r1), "=r"(r2), "=r"(r3) : "r"(addr))
#define MMA16816(c, a, b0, b1) \
    asm volatile("mma.sync.aligned.m16n8k16.row.col.f32.bf16.bf16.f32 " \
        "{%0,%1,%2,%3}, {%4,%5,%6,%7}, {%8,%9}, {%0,%1,%2,%3};" \
        : "+f"((c)[0]), "+f"((c)[1]), "+f"((c)[2]), "+f"((c)[3]) \
        : "r"((a)[0]), "r"((a)[1]), "r"((a)[2]), "r"((a)[3]), "r"(b0), "r"(b1))
#define MMAF16(c, a, b0, b1) \
    asm volatile("mma.sync.aligned.m16n8k16.row.col.f32.f16.f16.f32 " \
        "{%0,%1,%2,%3}, {%4,%5,%6,%7}, {%8,%9}, {%0,%1,%2,%3};" \
        : "+f"((c)[0]), "+f"((c)[1]), "+f"((c)[2]), "+f"((c)[3]) \
        : "r"((a)[0]), "r"((a)[1]), "r"((a)[2]), "r"((a)[3]), "r"(b0), "r"(b1))

__device__ __forceinline__ void split2(float x, float y, uint32_t& hi, uint32_t& lo) {
    __nv_bfloat16 hx = __float2bfloat16(x), hy = __float2bfloat16(y);
    __nv_bfloat16 lx = __float2bfloat16(x - __bfloat162float(hx));
    __nv_bfloat16 ly = __float2bfloat16(y - __bfloat162float(hy));
    __nv_bfloat162 h2(hx, hy), l2(lx, ly);
    hi = *(uint32_t*)&h2; lo = *(uint32_t*)&l2;
}
__device__ __forceinline__ uint32_t packh2(float x, float y) {
    __half2 h = __floats2half2_rn(x, y);
    return *(uint32_t*)&h;
}

// ================= conversions =================
__global__ __launch_bounds__(256)
void cvt_f16(const float4* __restrict__ in, __half* __restrict__ out, int n4)
{
    int base = blockIdx.x * 1024 + threadIdx.x;
    float4 f[4];
    int idx[4];
#pragma unroll
    for (int u = 0; u < 4; u++) {
        idx[u] = base + u * 256;
        if (idx[u] < n4) f[u] = in[idx[u]];
    }
#pragma unroll
    for (int u = 0; u < 4; u++) {
        if (idx[u] >= n4) continue;
        uint2 o;
        o.x = packh2(f[u].x, f[u].y);
        o.y = packh2(f[u].z, f[u].w);
        *(uint2*)(out + (size_t)idx[u] * 4) = o;
    }
}

__global__ __launch_bounds__(256)
void cvt_f16_w4(const float4* __restrict__ W0, const float4* __restrict__ W1,
                const float4* __restrict__ W2, const float4* __restrict__ W3,
                __half* __restrict__ out)
{
    const int n4 = Hh * Hh / 4;
    int z = blockIdx.y;
    const float4* in = (z == 0) ? W0 : (z == 1) ? W1 : (z == 2) ? W2 : W3;
    int base = blockIdx.x * 1024 + threadIdx.x;
    float4 f[4];
    int idx[4];
#pragma unroll
    for (int u = 0; u < 4; u++) {
        idx[u] = base + u * 256;
        if (idx[u] < n4) f[u] = in[idx[u]];
    }
    size_t zb = (size_t)z * Hh * Hh;
#pragma unroll
    for (int u = 0; u < 4; u++) {
        if (idx[u] >= n4) continue;
        uint2 o;
        o.x = packh2(f[u].x, f[u].y);
        o.y = packh2(f[u].z, f[u].w);
        *(uint2*)(out + zb + (size_t)idx[u] * 4) = o;
    }
}

// ================= fp16 single-term GEMM body: C = A @ W^T + b =================
#define GN 1024
#define GF_BUF 32768
#define GF_SMEM (2*GF_BUF + 512)

__device__ __forceinline__ void gemm_f16_body(
    const __half* __restrict__ Af, const __half* __restrict__ Wf,
    const float* __restrict__ bias, float oscale,
    __half* __restrict__ Ch, float* __restrict__ Cf,
    char* sm_, int bm, int bn)
{
    uint32_t sb = smem_u32(sm_);
    float* bias_s = (float*)(sm_ + 2 * GF_BUF);
    int tid = threadIdx.x, wid = tid >> 5, lid = tid & 31;
    if (tid < 128) bias_s[tid] = bias[bn + tid];

    int warp_row = (wid & 1) * 64;
    int warp_col = (wid >> 1) * 32;
    int sub = lid & 7;
    int gA1 = (lid >> 3) & 1, ca = (lid >> 4) & 1;
    int gB2 = (lid >> 4) & 1, cb = (lid >> 3) & 1;

    uint32_t aBase[4], bBase[2];
#pragma unroll
    for (int i = 0; i < 4; i++)
        aBase[i] = (uint32_t)((warp_row + i * 16 + gA1 * 8 + sub) * 128);
#pragma unroll
    for (int p = 0; p < 2; p++)
        bBase[p] = (uint32_t)((warp_col + p * 16 + gB2 * 8 + sub) * 128);

    float acc[4][4][4];
#pragma unroll
    for (int i = 0; i < 4; i++)
#pragma unroll
        for (int jn = 0; jn < 4; jn++)
#pragma unroll
            for (int r = 0; r < 4; r++) acc[i][jn][r] = 0.f;

#pragma unroll
    for (int i = tid; i < 1024; i += 256) {
        int r = i >> 3, c = i & 7;
        uint32_t sw = (uint32_t)(r * 128) + (uint32_t)((c ^ (r & 7)) << 4);
        CP_ASYNC16(sb + sw,           (const char*)Af + (((size_t)(bm + r)) << 11) + (c << 4));
        CP_ASYNC16(sb + 16384 + sw,   (const char*)Wf + (((size_t)(bn + r)) << 11) + (c << 4));
    }
    CP_COMMIT();

    for (int c = 0; c < 16; c++) {
        if (c + 1 < 16) {
            uint32_t nbuf = sb + ((c + 1) & 1) * GF_BUF;
            int kcb = (c + 1) * 128;
#pragma unroll
            for (int i = tid; i < 1024; i += 256) {
                int r = i >> 3, cc = i & 7;
                uint32_t sw = (uint32_t)(r * 128) + (uint32_t)((cc ^ (r & 7)) << 4);
                CP_ASYNC16(nbuf + sw,         (const char*)Af + (((size_t)(bm + r)) << 11) + kcb + (cc << 4));
                CP_ASYNC16(nbuf + 16384 + sw, (const char*)Wf + (((size_t)(bn + r)) << 11) + kcb + (cc << 4));
            }
            CP_COMMIT();
            CP_WAIT1();
        } else {
            CP_WAIT0();
        }
        __syncthreads();

        uint32_t bufoff = sb + (c & 1) * GF_BUF;
#pragma unroll
        for (int j = 0; j < 4; j++) {
            uint32_t ah[4][4], bh[2][4];
#pragma unroll
            for (int i = 0; i < 4; i++) {
                uint32_t ad = bufoff + aBase[i] + (uint32_t)(((2 * j + ca) ^ sub) << 4);
                LDSM_X4(ah[i][0], ah[i][1], ah[i][2], ah[i][3], ad);
            }
#pragma unroll
            for (int p = 0; p < 2; p++) {
                uint32_t bd = bufoff + 16384 + bBase[p] + (uint32_t)(((2 * j + cb) ^ sub) << 4);
                LDSM_X4(bh[p][0], bh[p][1], bh[p][2], bh[p][3], bd);
            }
#pragma unroll
            for (int i = 0; i < 4; i++) {
#pragma unroll
                for (int jn = 0; jn < 4; jn++) {
                    int p = jn >> 1, q = (jn & 1) * 2;
                    MMAF16(acc[i][jn], ah[i], bh[p][q], bh[p][q + 1]);
                }
            }
        }
        __syncthreads();
    }

    int lr = lid >> 2, lc = (lid & 3) * 2;
#pragma unroll
    for (int i = 0; i < 4; i++) {
#pragma unroll
        for (int jn = 0; jn < 4; jn++) {
            int row = bm + warp_row + i * 16 + lr;
            int colL = warp_col + jn * 8 + lc;
            int col = bn + colL;
            float b0 = bias_s[colL], b1 = bias_s[colL + 1];
            float v00 = (acc[i][jn][0] + b0) * oscale, v01 = (acc[i][jn][1] + b1) * oscale;
            float v10 = (acc[i][jn][2] + b0) * oscale, v11 = (acc[i][jn][3] + b1) * oscale;
            if (Ch) {
                *(uint32_t*)(Ch + (size_t)row * GN + col)       = packh2(v00, v01);
                *(uint32_t*)(Ch + (size_t)(row + 8) * GN + col) = packh2(v10, v11);
            } else {
                *(float2*)(Cf + (size_t)row * GN + col)       = make_float2(v00, v01);
                *(float2*)(Cf + (size_t)(row + 8) * GN + col) = make_float2(v10, v11);
            }
        }
    }
}

// ---------------- type-inference body (256 threads: 8 warps x 2 tokens) ----------------
__device__ __forceinline__ void type_body(
    const float* __restrict__ x, const float* __restrict__ Wti,
    const float* __restrict__ bti, const float* __restrict__ temb,
    const float* __restrict__ Wqt, const float* __restrict__ bqt,
    const float* __restrict__ Wkt, const float* __restrict__ bkt,
    float* __restrict__ tl_out, float* __restrict__ qt,
    __nv_bfloat16* __restrict__ kthi, __nv_bfloat16* __restrict__ ktlo,
    char* sm_, int bid)
{
    float* sWti  = (float*)sm_;               // NTt*Hh   = 5120
    float* stemb = sWti + NTt * Hh;           // NTt*HDd  = 320
    float* slat  = stemb + NTt * HDd;         // 8*HDd    = 512
    float* sWqt  = slat + 8 * HDd;            // HDd*65   = 4160
    float* sWkt  = sWqt + HDd * 65;           // HDd*65   = 4160  -> 57088 B total

    int tid = threadIdx.x, wid = tid >> 5, lid = tid & 31;
    for (int i = tid; i < NTt * Hh; i += 256) sWti[i] = Wti[i];
    for (int i = tid; i < NTt * HDd; i += 256) stemb[i] = temb[i];
    for (int i = tid; i < HDd * HDd; i += 256) {
        int r = i >> 6, c = i & 63;
        sWqt[r * 65 + c] = Wqt[i];
        sWkt[r * 65 + c] = Wkt[i];
    }
    __syncthreads();

    for (int tt = 0; tt < 2; tt++) {
        int tok = bid * 16 + wid * 2 + tt;
        const float* xr = x + (size_t)tok * Hh;
        float xv[32];
#pragma unroll
        for (int j = 0; j < 32; j++) xv[j] = xr[lid + 32 * j];

        float lg[NTt];
#pragma unroll
        for (int t = 0; t < NTt; t++) {
            float s = 0.f;
#pragma unroll
            for (int j = 0; j < 32; j++) s += xv[j] * sWti[t * Hh + lid + 32 * j];
            s += __shfl_xor_sync(0xffffffffu, s, 16);
            s += __shfl_xor_sync(0xffffffffu, s, 8);
            s += __shfl_xor_sync(0xffffffffu, s, 4);
            s += __shfl_xor_sync(0xffffffffu, s, 2);
            s += __shfl_xor_sync(0xffffffffu, s, 1);
            lg[t] = s + bti[t];
        }
        if (lid == 0) {
            float* tl = tl_out + (size_t)tok * NTt;
#pragma unroll
            for (int t = 0; t < NTt; t++) tl[t] = lg[t];
        }
        float mx = lg[0];
#pragma unroll
        for (int t = 1; t < NTt; t++) mx = fmaxf(mx, lg[t]);
        float e[NTt], se = 0.f;
#pragma unroll
        for (int t = 0; t < NTt; t++) { e[t] = expf(lg[t] - mx); se += e[t]; }
        float inv = 1.f / se;

        float la0 = 0.f, la1 = 0.f;
#pragma unroll
        for (int t = 0; t < NTt; t++) {
            float p = e[t] * inv;
            la0 += p * stemb[t * HDd + lid];
            la1 += p * stemb[t * HDd + lid + 32];
        }
        slat[wid * HDd + lid] = la0;
        slat[wid * HDd + lid + 32] = la1;
        __syncwarp();

#pragma unroll
        for (int rep = 0; rep < 2; rep++) {
            int d = lid + rep * 32;
            float a = bqt[d], c = bkt[d];
            const float* wq = sWqt + d * 65;
            const float* wk = sWkt + d * 65;
            const float* la = slat + wid * HDd;
#pragma unroll
            for (int e2 = 0; e2 < HDd; e2++) {
                float lv = la[e2];
                a += lv * wq[e2];
                c += lv * wk[e2];
            }
            qt[(size_t)tok * HDd + d] = a;
            __nv_bfloat16 hc = __float2bfloat16(c);
            kthi[(size_t)tok * HDd + d] = hc;
            ktlo[(size_t)tok * HDd + d] = __float2bfloat16(c - __bfloat162float(hc));
        }
        __syncwarp();   // slat reused next iteration
    }
}

// fused Q/K/V projection + type inference: grid (8, 32, 4); z in {0,1,2}=QKV, z==3=type
__global__ __launch_bounds__(256)
void gemm_qkv_type(const __half* __restrict__ xf, const __half* __restrict__ wf,
                   const float* __restrict__ bq, const float* __restrict__ bk,
                   const float* __restrict__ bv,
                   __half* __restrict__ qf, __half* __restrict__ kf, __half* __restrict__ vf,
                   const float* __restrict__ x, const float* __restrict__ Wti,
                   const float* __restrict__ bti, const float* __restrict__ temb,
                   const float* __restrict__ Wqt, const float* __restrict__ bqt,
                   const float* __restrict__ Wkt, const float* __restrict__ bkt,
                   float* __restrict__ tl_out, float* __restrict__ qt,
                   __nv_bfloat16* __restrict__ kthi, __nv_bfloat16* __restrict__ ktlo)
{
    extern __shared__ char sm_[];
    int z = blockIdx.z;
    if (z < 3) {
        const __half* Wf = wf + (size_t)z * Hh * Hh;
        const float* bias = (z == 0) ? bq : (z == 1) ? bk : bv;
        __half* Ch = (z == 0) ? qf : (z == 1) ? kf : vf;
        float oscale = (z == 0) ? SCALE : 1.f;
        gemm_f16_body(xf, Wf, bias, oscale, Ch, nullptr, sm_,
                      blockIdx.y * 128, blockIdx.x * 128);
    } else {
        int bid = blockIdx.y * 8 + blockIdx.x;   // 0..255, 16 tokens each
        type_body(x, Wti, bti, temb, Wqt, bqt, Wkt, bkt,
                  tl_out, qt, kthi, ktlo, sm_, bid);
    }
}

// O projection: fp16 inputs, fp32 output
__global__ __launch_bounds__(256)
void gemm_o_f16(const __half* __restrict__ of, const __half* __restrict__ wf,
                const float* __restrict__ bias, float* __restrict__ Cf)
{
    extern __shared__ char sm_[];
    gemm_f16_body(of, wf + (size_t)3 * Hh * Hh, bias, 1.f, nullptr, Cf, sm_,
                  blockIdx.y * 128, blockIdx.x * 128);
}

// ---------------- qtW (pre-scaled by 1/8, exact) ----------------
__global__ __launch_bounds__(256)
void qtw_kernel(const float* __restrict__ qt, const float* __restrict__ Wb,
                __nv_bfloat16* __restrict__ qwhi, __nv_bfloat16* __restrict__ qwlo)
{
    __shared__ float Qs[64][65];
    __shared__ float Ws[64][65];
    int h = blockIdx.y;
    int t0 = blockIdx.x * 64;
    int tid = threadIdx.x;
    for (int i = tid; i < 4096; i += 256) {
        int r = i >> 6, c = i & 63;
        Qs[r][c] = qt[(size_t)(t0 + r) * HDd + c];
        Ws[r][c] = Wb[(size_t)h * 4096 + i];
    }
    __syncthreads();
    int tx = tid & 15, ty = tid >> 4;
    float acc[4][4];
#pragma unroll
    for (int i = 0; i < 4; i++)
#pragma unroll
        for (int j = 0; j < 4; j++) acc[i][j] = 0.f;
#pragma unroll 4
    for (int d = 0; d < 64; d++) {
        float a[4], b[4];
#pragma unroll
        for (int i = 0; i < 4; i++) a[i] = Qs[ty * 4 + i][d];
#pragma unroll
        for (int j = 0; j < 4; j++) b[j] = Ws[d][tx * 4 + j];
#pragma unroll
        for (int i = 0; i < 4; i++)
#pragma unroll
            for (int j = 0; j < 4; j++) acc[i][j] += a[i] * b[j];
    }
#pragma unroll
    for (int i = 0; i < 4; i++) {
        int tok = t0 + ty * 4 + i;
        int b = tok >> 11;
        int qq = tok & 2047;
        size_t base = (((size_t)(b * NHh + h)) * Ss + qq) * HDd + tx * 4;
        uint32_t h0, l0, h1, l1;
        split2(acc[i][0] * SCALE, acc[i][1] * SCALE, h0, l0);
        split2(acc[i][2] * SCALE, acc[i][3] * SCALE, h1, l1);
        uint2 hv = make_uint2(h0, h1), lv = make_uint2(l0, l1);
        *(uint2*)(qwhi + base) = hv;
        *(uint2*)(qwlo + base) = lv;
    }
}

// ================= HMMA flash attention v5 (fp32 elementwise, fp16 epilogue) =================
#define AKV 16512
#define ATT_QREG 24576
#define ATT_SMEM (ATT_QREG + 2*AKV)   /* 57600 */
#define NKT (Ss/32)

__device__ __forceinline__ void att_load_kv(uint32_t dst, int b, int h, int k0, int tid,
    const __half* kf, const __nv_bfloat16* kthi, const __nv_bfloat16* ktlo,
    const __half* vf, const int* mask)
{
#pragma unroll
    for (int i = tid; i < 256; i += 128) {
        int r = i >> 3, c = i & 7;
        uint32_t sw = (uint32_t)(r * 128) + (uint32_t)((c ^ (r & 7)) << 4);
        size_t gk = ((size_t)(b * Ss + k0 + r)) * 2048 + h * 128 + (c << 4);
        size_t gt = ((size_t)(b * Ss + k0 + r)) * 128 + (c << 4);
        CP_ASYNC16(dst + sw,          (const char*)kf + gk);
        CP_ASYNC16(dst + 4096 + sw,   (const char*)kthi + gt);
        CP_ASYNC16(dst + 8192 + sw,   (const char*)ktlo + gt);
        CP_ASYNC16(dst + 12288 + sw,  (const char*)vf + gk);
    }
    if (tid < 8)
        CP_ASYNC16(dst + 16384 + tid * 16, (const char*)mask + ((size_t)(b * Ss + k0)) * 4 + tid * 16);
}

__global__ __launch_bounds__(128, 3)
void attn_hmma(const __half* __restrict__ qf, const __half* __restrict__ kf,
               const __half* __restrict__ vf,
               const __nv_bfloat16* __restrict__ kthi, const __nv_bfloat16* __restrict__ ktlo,
               const __nv_bfloat16* __restrict__ qwhi, const __nv_bfloat16* __restrict__ qwlo,
               const int* __restrict__ mask, float* __restrict__ unif,
               __half* __restrict__ of)
{
    extern __shared__ char sm_[];
    uint32_t sb = smem_u32(sm_);
    int tid = threadIdx.x, wid = tid >> 5, lid = tid & 31;
    int b = blockIdx.z, h = blockIdx.y, q0 = blockIdx.x * 64;
    const float NEGINF = __int_as_float(0xff800000);

#pragma unroll
    for (int i = tid; i < 512; i += 128) {
        int r = i >> 3, c = i & 7;
        uint32_t sw = (uint32_t)(r * 128) + (uint32_t)((c ^ (r & 7)) << 4);
        size_t gq = ((size_t)(b * Ss + q0 + r)) * 2048 + h * 128 + (c << 4);
        size_t gw = (((size_t)(b * NHh + h)) * Ss + q0 + r) * 128 + (c << 4);
        CP_ASYNC16(sb + sw,          (const char*)qf + gq);
        CP_ASYNC16(sb + 8192 + sw,   (const char*)qwhi + gw);
        CP_ASYNC16(sb + 16384 + sw,  (const char*)qwlo + gw);
    }
    att_load_kv(sb + ATT_QREG, b, h, 0, tid, kf, kthi, ktlo, vf, mask);
    CP_COMMIT();

    int sub = lid & 7;
    int gA1 = (lid >> 3) & 1, ca = (lid >> 4) & 1;
    int gB2 = (lid >> 4) & 1, cb = (lid >> 3) & 1;
    int arow = wid * 16 + gA1 * 8 + sub;
    uint32_t aoffQ[4];
#pragma unroll
    for (int j = 0; j < 4; j++)
        aoffQ[j] = (uint32_t)(arow * 128) + (uint32_t)(((2 * j + ca) ^ sub) << 4);

    uint32_t qfr[4][4];
    float out[32], sv[16], su[16];
    float lsum0 = 0.f, lsum1 = 0.f;
#pragma unroll
    for (int i = 0; i < 32; i++) out[i] = 0.f;

    int row0 = q0 + wid * 16 + (lid >> 2);
    int mcol = 2 * (lid & 3);

    for (int kt = 0; kt < NKT; kt++) {
        if (kt + 1 < NKT) {
            att_load_kv(sb + ATT_QREG + ((kt + 1) & 1) * AKV, b, h, (kt + 1) * 32, tid,
                        kf, kthi, ktlo, vf, mask);
            CP_COMMIT();
            CP_WAIT1();
        } else {
            CP_WAIT0();
        }
        __syncthreads();

        if (kt == 0) {
#pragma unroll
            for (int j = 0; j < 4; j++)
                LDSM_X4(qfr[j][0], qfr[j][1], qfr[j][2], qfr[j][3], sb + aoffQ[j]);
        }

        uint32_t cbuf = sb + ATT_QREG + (kt & 1) * AKV;
        int k0 = kt * 32;
#pragma unroll
        for (int i = 0; i < 16; i++) { sv[i] = 0.f; su[i] = 0.f; }

        // ---- val scores: Q . K^T  (fp16 single-term, Q pre-scaled by 1/8) ----
#pragma unroll
        for (int j = 0; j < 4; j++) {
            uint32_t bh[8];
#pragma unroll
            for (int p = 0; p < 2; p++) {
                uint32_t bo = (uint32_t)((p * 16 + gB2 * 8 + sub) * 128)
                            + (uint32_t)(((2 * j + cb) ^ sub) << 4);
                LDSM_X4(bh[4*p], bh[4*p+1], bh[4*p+2], bh[4*p+3], cbuf + bo);
            }
#pragma unroll
            for (int jn = 0; jn < 4; jn++) {
                int bi = (jn >> 1) * 4 + (jn & 1) * 2;
                MMAF16(sv + 4*jn, qfr[j], bh[bi], bh[bi+1]);
            }
        }
        // ---- unif scores: QW . KT^T  (bf16 3-term) ----
#pragma unroll
        for (int j = 0; j < 4; j++) {
            uint32_t aw_h[4], aw_l[4], bh[8], bl[8];
            LDSM_X4(aw_h[0], aw_h[1], aw_h[2], aw_h[3], sb + 8192 + aoffQ[j]);
            LDSM_X4(aw_l[0], aw_l[1], aw_l[2], aw_l[3], sb + 16384 + aoffQ[j]);
#pragma unroll
            for (int p = 0; p < 2; p++) {
                uint32_t bo = (uint32_t)((p * 16 + gB2 * 8 + sub) * 128)
                            + (uint32_t)(((2 * j + cb) ^ sub) << 4);
                LDSM_X4(bh[4*p], bh[4*p+1], bh[4*p+2], bh[4*p+3], cbuf + 4096 + bo);
                LDSM_X4(bl[4*p], bl[4*p+1], bl[4*p+2], bl[4*p+3], cbuf + 8192 + bo);
            }
#pragma unroll
            for (int jn = 0; jn < 4; jn++) {
                int bi = (jn >> 1) * 4 + (jn & 1) * 2;
                MMA16816(su + 4*jn, aw_h, bh[bi], bh[bi+1]);
                MMA16816(su + 4*jn, aw_h, bl[bi], bl[bi+1]);
                MMA16816(su + 4*jn, aw_l, bh[bi], bh[bi+1]);
            }
        }

        // ---- elementwise (fp32 MUFU): unif store, mask, p = exp(s)*(sigmoid(u)+1e-6) ----
        const char* mbuf = sm_ + ATT_QREG + (kt & 1) * AKV + 16384;
        uint32_t pa[2][4];
#pragma unroll
        for (int jn = 0; jn < 4; jn++) {
            int colL = jn * 8 + mcol;
            size_t ub = (((size_t)(b * NHh + h)) * Ss + row0) * Ss + k0 + colL;
            *(float2*)(unif + ub)          = make_float2(su[4*jn],   su[4*jn+1]);
            *(float2*)(unif + ub + 8 * Ss) = make_float2(su[4*jn+2], su[4*jn+3]);
            int2 mk = *(const int2*)(mbuf + colL * 4);
            float s0 = mk.x ? sv[4*jn]   : NEGINF;
            float s1 = mk.y ? sv[4*jn+1] : NEGINF;
            float s2 = mk.x ? sv[4*jn+2] : NEGINF;
            float s3 = mk.y ? sv[4*jn+3] : NEGINF;
            float g0 = __fdividef(1.f, 1.f + __expf(-su[4*jn]))   + 1e-6f;
            float g1 = __fdividef(1.f, 1.f + __expf(-su[4*jn+1])) + 1e-6f;
            float g2 = __fdividef(1.f, 1.f + __expf(-su[4*jn+2])) + 1e-6f;
            float g3 = __fdividef(1.f, 1.f + __expf(-su[4*jn+3])) + 1e-6f;
            float p0 = __expf(s0) * g0;
            float p1 = __expf(s1) * g1;
            float p2 = __expf(s2) * g2;
            float p3 = __expf(s3) * g3;
            lsum0 += p0 + p1;
            lsum1 += p2 + p3;
            int t = jn >> 1, o = (jn & 1) * 2;
            pa[t][o]     = packh2(p0, p1);
            pa[t][o + 1] = packh2(p2, p3);
        }

        // ---- PV: out += P . V  (fp16 single-term) ----
#pragma unroll
        for (int t = 0; t < 2; t++) {
#pragma unroll
            for (int g = 0; g < 4; g++) {
                uint32_t vro = (uint32_t)((t * 16 + (lid & 15)) * 128)
                             + (uint32_t)(((2 * g + ((lid >> 4) & 1)) ^ (lid & 7)) << 4);
                uint32_t vh[4];
                LDSM_X4_T(vh[0], vh[1], vh[2], vh[3], cbuf + 12288 + vro);
                MMAF16(out + 4*(2*g),   pa[t], vh[0], vh[1]);
                MMAF16(out + 4*(2*g+1), pa[t], vh[2], vh[3]);
            }
        }
        __syncthreads();
    }

    lsum0 += __shfl_xor_sync(0xffffffffu, lsum0, 1);
    lsum0 += __shfl_xor_sync(0xffffffffu, lsum0, 2);
    lsum1 += __shfl_xor_sync(0xffffffffu, lsum1, 1);
    lsum1 += __shfl_xor_sync(0xffffffffu, lsum1, 2);
    float i0 = 1.f / lsum0, i1 = 1.f / lsum1;
    size_t r0g = (size_t)(b * Ss + row0);
#pragma unroll
    for (int dn = 0; dn < 8; dn++) {
        int col = h * 64 + dn * 8 + mcol;
        *(uint32_t*)(of + r0g * Hh + col)       = packh2(out[4*dn] * i0,   out[4*dn+1] * i0);
        *(uint32_t*)(of + (r0g + 8) * Hh + col) = packh2(out[4*dn+2] * i1, out[4*dn+3] * i1);
    }
}

// ---------------- launch ----------------
extern "C" void kernel_launch(void* const* d_in, const int* in_sizes, int n_in,
                              void* d_out, int out_size)
{
    (void)in_sizes; (void)n_in; (void)out_size;
    const float* x    = (const float*)d_in[0];
    const int*   mask = (const int*)  d_in[1];
    const float* Wq   = (const float*)d_in[2];
    const float* bq   = (const float*)d_in[3];
    const float* Wk   = (const float*)d_in[4];
    const float* bk   = (const float*)d_in[5];
    const float* Wv   = (const float*)d_in[6];
    const float* bv   = (const float*)d_in[7];
    const float* Wo   = (const float*)d_in[8];
    const float* bo   = (const float*)d_in[9];
    const float* Wti  = (const float*)d_in[10];
    const float* bti  = (const float*)d_in[11];
    const float* temb = (const float*)d_in[12];
    const float* Wqt  = (const float*)d_in[13];
    const float* bqt  = (const float*)d_in[14];
    const float* Wkt  = (const float*)d_in[15];
    const float* bkt  = (const float*)d_in[16];
    const float* Wbil = (const float*)d_in[17];

    float* out      = (float*)d_out;
    float* out_y    = out;
    float* out_tl   = out + (size_t)TOKS * Hh;
    float* out_unif = out_tl + (size_t)TOKS * NTt;

    float* qt;
    __nv_bfloat16 *kth, *ktl, *qwh, *qwl;
    __half *xf, *wf, *qfp, *kfp, *vfp;
    cudaGetSymbolAddress((void**)&qt,   g_qt);
    cudaGetSymbolAddress((void**)&xf,   g_xf);
    cudaGetSymbolAddress((void**)&wf,   g_wf);
    cudaGetSymbolAddress((void**)&qfp,  g_qf);
    cudaGetSymbolAddress((void**)&kfp,  g_kf);
    cudaGetSymbolAddress((void**)&vfp,  g_vf);
    cudaGetSymbolAddress((void**)&kth,  g_kthi);
    cudaGetSymbolAddress((void**)&ktl,  g_ktlo);
    cudaGetSymbolAddress((void**)&qwh,  g_qwhi);
    cudaGetSymbolAddress((void**)&qwl,  g_qwlo);

    const size_t WSZ = (size_t)Hh * Hh;
    cvt_f16<<<(TOKS * Hh / 4 + 1023) / 1024, 256>>>((const float4*)x, xf, TOKS * Hh / 4);
    cvt_f16_w4<<<dim3((WSZ / 4 + 1023) / 1024, 4), 256>>>(
        (const float4*)Wq, (const float4*)Wk, (const float4*)Wv, (const float4*)Wo, wf);

    cudaFuncSetAttribute(gemm_qkv_type, cudaFuncAttributeMaxDynamicSharedMemorySize, GF_SMEM);
    cudaFuncSetAttribute(gemm_o_f16,    cudaFuncAttributeMaxDynamicSharedMemorySize, GF_SMEM);
    // z in {0,1,2}: Q/K/V projections (128x128 tiles); z==3: type inference (16 tokens/block)
    gemm_qkv_type<<<dim3(GN / 128, TOKS / 128, 4), 256, GF_SMEM>>>(
        xf, wf, bq, bk, bv, qfp, kfp, vfp,
        x, Wti, bti, temb, Wqt, bqt, Wkt, bkt, out_tl, qt, kth, ktl);

    qtw_kernel<<<dim3(TOKS / 64, NHh), 256>>>(qt, Wbil, qwh, qwl);

    cudaFuncSetAttribute(attn_hmma, cudaFuncAttributeMaxDynamicSharedMemorySize, ATT_SMEM);
    attn_hmma<<<dim3(Ss / 64, NHh, Bb), 128, ATT_SMEM>>>(qfp, kfp, vfp,
        kth, ktl, qwh, qwl, mask, out_unif, xf);

    gemm_o_f16<<<dim3(GN / 128, TOKS / 128), 256, GF_SMEM>>>(xf, wf, bo, out_y);
}